// round 2
// baseline (speedup 1.0000x reference)
#include <cuda_runtime.h>
#include <cstdint>

// Problem constants
#define BB 8
#define SS 1024
#define DD 1024
#define HH 16
#define DHH 64
#define QKVN 3072          // 3 * H * DH
#define MROWS 8192         // B * S
#define KDIM 1024

// ---------------- scratch (static device globals; no runtime allocation) ----
__device__ float g_w[KDIM * QKVN];                 // packed QKV weights [D][3072]
__device__ float g_b[QKVN];                        // packed QKV bias
__device__ float g_qkv[(size_t)MROWS * QKVN];      // Q|K|V per row (96 MB)
__device__ float g_ctx[(size_t)MROWS * DD];        // attention output (33.5 MB)

// ---------------- pack Wq/Wk/Wv [H,D,DH] -> g_w [D][3*H*DH], bias likewise --
__global__ void pack_w_kernel(const float* __restrict__ Wq, const float* __restrict__ bq,
                              const float* __restrict__ Wk, const float* __restrict__ bk,
                              const float* __restrict__ Wv, const float* __restrict__ bv)
{
    int idx = blockIdx.x * 256 + threadIdx.x;
    if (idx < KDIM * QKVN) {
        int d   = idx / QKVN;
        int col = idx - d * QKVN;
        int which = col >> 10;          // 0:Q 1:K 2:V
        int he  = col & 1023;           // h*64 + e
        int h   = he >> 6;
        int e   = he & 63;
        const float* W = (which == 0) ? Wq : ((which == 1) ? Wk : Wv);
        g_w[idx] = W[(h * KDIM + d) * DHH + e];
    }
    if (idx < QKVN) {
        int which = idx >> 10;
        int he = idx & 1023;
        const float* bb = (which == 0) ? bq : ((which == 1) ? bk : bv);
        g_b[idx] = bb[he];
    }
}

// ---------------- SGEMM: C[M][N] = A[M][K] @ Bm[K][N] + bias[N] -------------
// 128x128 block tile, BK=8, 256 threads, 8x8 per-thread register tile.
__global__ __launch_bounds__(256, 2)
void sgemm_bias_kernel(const float* __restrict__ A, const float* __restrict__ Bm,
                       const float* __restrict__ bias, float* __restrict__ C,
                       int M, int N, int K)
{
    __shared__ float As[8][128];
    __shared__ float Bs[8][128];

    const int tid = threadIdx.x;
    const int bm = blockIdx.y * 128;
    const int bn = blockIdx.x * 128;
    const int ty = tid >> 4;        // 0..15
    const int tx = tid & 15;        // 0..15

    const int arow = tid >> 1;          // 0..127
    const int acol = (tid & 1) * 4;     // 0 or 4
    const int brow = tid >> 5;          // 0..7
    const int bcol = (tid & 31) * 4;    // 0..124

    const float* Ap = A + (size_t)(bm + arow) * K + acol;
    const float* Bp = Bm + (size_t)brow * N + bn + bcol;

    float acc[8][8];
#pragma unroll
    for (int i = 0; i < 8; i++)
#pragma unroll
        for (int j = 0; j < 8; j++) acc[i][j] = 0.f;

    for (int k0 = 0; k0 < K; k0 += 8) {
        float4 av = *(const float4*)Ap;
        As[acol + 0][arow] = av.x;
        As[acol + 1][arow] = av.y;
        As[acol + 2][arow] = av.z;
        As[acol + 3][arow] = av.w;
        *(float4*)&Bs[brow][bcol] = *(const float4*)Bp;
        Ap += 8;
        Bp += (size_t)8 * N;
        __syncthreads();

#pragma unroll
        for (int k = 0; k < 8; k++) {
            float ar[8], br[8];
            *(float4*)&ar[0] = *(const float4*)&As[k][ty * 8];
            *(float4*)&ar[4] = *(const float4*)&As[k][ty * 8 + 4];
            *(float4*)&br[0] = *(const float4*)&Bs[k][tx * 8];
            *(float4*)&br[4] = *(const float4*)&Bs[k][tx * 8 + 4];
#pragma unroll
            for (int i = 0; i < 8; i++)
#pragma unroll
                for (int j = 0; j < 8; j++)
                    acc[i][j] += ar[i] * br[j];
        }
        __syncthreads();
    }

    float bvv[8];
#pragma unroll
    for (int j = 0; j < 8; j++) bvv[j] = bias[bn + tx * 8 + j];

#pragma unroll
    for (int i = 0; i < 8; i++) {
        float* Cp = C + (size_t)(bm + ty * 8 + i) * N + bn + tx * 8;
        float4 o0, o1;
        o0.x = acc[i][0] + bvv[0]; o0.y = acc[i][1] + bvv[1];
        o0.z = acc[i][2] + bvv[2]; o0.w = acc[i][3] + bvv[3];
        o1.x = acc[i][4] + bvv[4]; o1.y = acc[i][5] + bvv[5];
        o1.z = acc[i][6] + bvv[6]; o1.w = acc[i][7] + bvv[7];
        *(float4*)(Cp)     = o0;
        *(float4*)(Cp + 4) = o1;
    }
}

// ---------------- fused masked-softmax attention (flash-style) --------------
// grid: (S/16, B*H). block: 256 threads. Each block: 16 query rows, full head.
// Thread (r = tid>>4, c = tid&15): row r, dh columns c*4..c*4+3 of the output;
// in score space, key columns c*4..c*4+3 of the current 64-key chunk.
__global__ __launch_bounds__(256)
void attn_kernel(const int* __restrict__ mask)   // mask is int32 (bool -> int32)
{
    __shared__ float qs[16][64];
    __shared__ float kt[64][68];   // transposed K chunk, padded
    __shared__ float vs[64][64];
    __shared__ float ps[16][68];   // probabilities, padded

    const int tid = threadIdx.x;
    const int bh = blockIdx.y;
    const int b = bh >> 4;
    const int h = bh & 15;
    const int q0 = blockIdx.x * 16;
    const int r = tid >> 4;
    const int c = tid & 15;

    // load Q tile, scale folded in (1/sqrt(D) = 1/32)
    {
        const int kk = c * 4;
        float4 v = *(const float4*)(g_qkv + (size_t)(b * SS + q0 + r) * QKVN + h * DHH + kk);
        qs[r][kk + 0] = v.x * 0.03125f;
        qs[r][kk + 1] = v.y * 0.03125f;
        qs[r][kk + 2] = v.z * 0.03125f;
        qs[r][kk + 3] = v.w * 0.03125f;
    }

    float m = -1e30f, l = 0.f;
    float o0 = 0.f, o1 = 0.f, o2 = 0.f, o3 = 0.f;

    const int lkey = tid >> 2;        // 0..63
    const int lk0  = (tid & 3) * 16;  // 0,16,32,48

    for (int j = 0; j < 16; j++) {
        __syncthreads();
        // K chunk (transposed into smem) and V chunk
        {
            const float* kp = g_qkv + (size_t)(b * SS + j * 64 + lkey) * QKVN + 1024 + h * DHH + lk0;
#pragma unroll
            for (int i = 0; i < 4; i++) {
                float4 kv = *(const float4*)(kp + i * 4);
                kt[lk0 + i * 4 + 0][lkey] = kv.x;
                kt[lk0 + i * 4 + 1][lkey] = kv.y;
                kt[lk0 + i * 4 + 2][lkey] = kv.z;
                kt[lk0 + i * 4 + 3][lkey] = kv.w;
            }
            const float* vp = g_qkv + (size_t)(b * SS + j * 64 + lkey) * QKVN + 2048 + h * DHH + lk0;
#pragma unroll
            for (int i = 0; i < 4; i++)
                *(float4*)&vs[lkey][lk0 + i * 4] = *(const float4*)(vp + i * 4);
        }
        __syncthreads();

        // GEMM1: s[r][c*4..+3] = (scaled Q row r) . K cols
        float s0 = 0.f, s1 = 0.f, s2 = 0.f, s3 = 0.f;
#pragma unroll
        for (int k = 0; k < 64; k++) {
            float qv = qs[r][k];
            float4 kv = *(const float4*)&kt[k][c * 4];
            s0 += qv * kv.x; s1 += qv * kv.y; s2 += qv * kv.z; s3 += qv * kv.w;
        }

        // mask (nonzero -> -1e9), matches reference semantics incl. fully-masked rows
        int4 mk = *(const int4*)(mask + (size_t)b * SS * SS + (size_t)(q0 + r) * SS + j * 64 + c * 4);
        if (mk.x) s0 = -1e9f;
        if (mk.y) s1 = -1e9f;
        if (mk.z) s2 = -1e9f;
        if (mk.w) s3 = -1e9f;

        // online softmax across the 16-thread row group
        float smax = fmaxf(fmaxf(s0, s1), fmaxf(s2, s3));
#pragma unroll
        for (int off = 8; off > 0; off >>= 1)
            smax = fmaxf(smax, __shfl_xor_sync(0xffffffffu, smax, off, 16));
        float mnew = fmaxf(m, smax);
        float alpha = __expf(m - mnew);
        float p0 = __expf(s0 - mnew);
        float p1 = __expf(s1 - mnew);
        float p2 = __expf(s2 - mnew);
        float p3 = __expf(s3 - mnew);
        float psum = p0 + p1 + p2 + p3;
#pragma unroll
        for (int off = 8; off > 0; off >>= 1)
            psum += __shfl_xor_sync(0xffffffffu, psum, off, 16);
        l = l * alpha + psum;
        m = mnew;
        o0 *= alpha; o1 *= alpha; o2 *= alpha; o3 *= alpha;

        *(float4*)&ps[r][c * 4] = make_float4(p0, p1, p2, p3);
        __syncwarp();

        // GEMM2: o += P_chunk @ V_chunk
#pragma unroll
        for (int ck = 0; ck < 64; ck++) {
            float p = ps[r][ck];
            float4 vv = *(const float4*)&vs[ck][c * 4];
            o0 += p * vv.x; o1 += p * vv.y; o2 += p * vv.z; o3 += p * vv.w;
        }
    }

    float inv = 1.f / l;
    float4 out = make_float4(o0 * inv, o1 * inv, o2 * inv, o3 * inv);
    // write as [B, S, H*DH] so output projection is a plain GEMM
    *(float4*)(g_ctx + (size_t)(b * SS + q0 + r) * DD + h * DHH + c * 4) = out;
}

// ---------------- launch ----------------------------------------------------
extern "C" void kernel_launch(void* const* d_in, const int* in_sizes, int n_in,
                              void* d_out, int out_size)
{
    const float* x  = (const float*)d_in[0];
    const int* mask = (const int*)d_in[1];      // bool -> int32 in harness
    const float* Wq = (const float*)d_in[2];
    const float* bq = (const float*)d_in[3];
    const float* Wk = (const float*)d_in[4];
    const float* bk = (const float*)d_in[5];
    const float* Wv = (const float*)d_in[6];
    const float* bv = (const float*)d_in[7];
    const float* Wo = (const float*)d_in[8];
    const float* bo = (const float*)d_in[9];
    float* out = (float*)d_out;

    void *p_w, *p_b, *p_qkv, *p_ctx;
    cudaGetSymbolAddress(&p_w, g_w);
    cudaGetSymbolAddress(&p_b, g_b);
    cudaGetSymbolAddress(&p_qkv, g_qkv);
    cudaGetSymbolAddress(&p_ctx, g_ctx);

    // 1) pack per-head projection weights into one [1024 x 3072] matrix
    pack_w_kernel<<<(KDIM * QKVN + 255) / 256, 256>>>(Wq, bq, Wk, bk, Wv, bv);

    // 2) QKV projection: [8192x1024] @ [1024x3072] + bias
    sgemm_bias_kernel<<<dim3(QKVN / 128, MROWS / 128), 256>>>(
        x, (const float*)p_w, (const float*)p_b, (float*)p_qkv, MROWS, QKVN, KDIM);

    // 3) fused masked attention -> g_ctx [8192 x 1024]
    attn_kernel<<<dim3(SS / 16, BB * HH), 256>>>(mask);

    // 4) output projection: [8192x1024] @ [1024x1024] + bo
    sgemm_bias_kernel<<<dim3(DD / 128, MROWS / 128), 256>>>(
        (const float*)p_ctx, Wo, bo, out, MROWS, DD, KDIM);
}

// round 3
// speedup vs baseline: 2.5838x; 2.5838x over previous
#include <cuda_runtime.h>
#include <cstdint>

#define BB 8
#define SS 1024
#define DD 1024
#define HH 16
#define DHH 64
#define QKVN 3072
#define MROWS 8192
#define KDIM 1024

// ---------------- scratch ----------------------------------------------------
__device__ float g_w[KDIM * QKVN];
__device__ float g_b[QKVN];
__device__ float g_qkv[(size_t)MROWS * QKVN];
__device__ float g_ctx[(size_t)MROWS * DD];

// ---------------- pack Wq/Wk/Wv [H,D,DH] -> g_w [D][3*H*DH] ------------------
__global__ void pack_w_kernel(const float* __restrict__ Wq, const float* __restrict__ bq,
                              const float* __restrict__ Wk, const float* __restrict__ bk,
                              const float* __restrict__ Wv, const float* __restrict__ bv)
{
    int idx = blockIdx.x * 256 + threadIdx.x;
    if (idx < KDIM * QKVN) {
        int d   = idx / QKVN;
        int col = idx - d * QKVN;
        int which = col >> 10;
        int he  = col & 1023;
        int h   = he >> 6;
        int e   = he & 63;
        const float* W = (which == 0) ? Wq : ((which == 1) ? Wk : Wv);
        g_w[idx] = W[(h * KDIM + d) * DHH + e];
    }
    if (idx < QKVN) {
        int which = idx >> 10;
        int he = idx & 1023;
        const float* bb = (which == 0) ? bq : ((which == 1) ? bk : bv);
        g_b[idx] = bb[he];
    }
}

// ---------------- tf32 tensor-core GEMM + bias -------------------------------
// C[M][N] = A[M][K] @ B[K][N] + bias. 128x128 tile, BK=16, 256 threads,
// 8 warps in 2x4, each warp 64x32 via 4x4 grid of m16n8k8 tf32 mma.
// Smem tiles stored FRAGMENT-MAJOR so frag loads are single LDS.128/LDS.64.

__device__ __forceinline__ unsigned f2tf32(float x) {
    unsigned u;
    asm("cvt.rna.tf32.f32 %0, %1;" : "=r"(u) : "f"(x));
    return u;
}

#define MMA_TF32(c, a, b)                                                     \
    asm volatile("mma.sync.aligned.m16n8k8.row.col.f32.tf32.tf32.f32 "        \
                 "{%0,%1,%2,%3}, {%4,%5,%6,%7}, {%8,%9}, {%0,%1,%2,%3};"      \
                 : "+f"((c)[0]), "+f"((c)[1]), "+f"((c)[2]), "+f"((c)[3])     \
                 : "r"((a).x), "r"((a).y), "r"((a).z), "r"((a).w),            \
                   "r"((b).x), "r"((b).y))

__global__ __launch_bounds__(256, 2)
void tf32_gemm_bias(const float* __restrict__ A, const float* __restrict__ Bm,
                    const float* __restrict__ bias, float* __restrict__ C,
                    int M, int N, int K)
{
    __shared__ unsigned As[2][2][8][128];   // [buf][kslab][msub16][lane*4+slot]
    __shared__ unsigned Bs[2][2][16][66];   // [buf][kslab][nsub8][lane*2+slot] (+pad)

    const int tid  = threadIdx.x;
    const int lane = tid & 31;
    const int wid  = tid >> 5;
    const int wm   = wid >> 2;          // 0..1
    const int wn   = wid & 3;           // 0..3
    const int bm   = blockIdx.y * 128;
    const int bn   = blockIdx.x * 128;

    const int arow = tid >> 2;          // 0..63 (and +64)
    const int acg  = (tid & 3) * 4;     // 0,4,8,12
    const int bkr  = tid >> 4;          // 0..15
    const int bnc0 = (tid & 15) * 8;    // 0..120

    float acc[4][4][4];
#pragma unroll
    for (int m = 0; m < 4; m++)
#pragma unroll
        for (int n = 0; n < 4; n++)
#pragma unroll
            for (int e = 0; e < 4; e++) acc[m][n][e] = 0.f;

    float a_st[2][4], b_st[2][4];

    // ---- first tile: LDG + STS
#pragma unroll
    for (int i = 0; i < 2; i++) {
        *(float4*)a_st[i] = *(const float4*)&A[(size_t)(bm + arow + i * 64) * K + acg];
        *(float4*)b_st[i] = *(const float4*)&Bm[(size_t)(bkr) * N + bn + bnc0 + i * 4];
    }
    {
#pragma unroll
        for (int i = 0; i < 2; i++) {
            int row = arow + i * 64, msub = row >> 4, r = row & 15;
#pragma unroll
            for (int e = 0; e < 4; e++) {
                int c = acg + e, slab = c >> 3, cc = c & 7;
                int ln = ((r & 7) << 2) | (cc & 3);
                int slot = ((r >> 3) & 1) | ((cc >> 2) << 1);
                As[0][slab][msub][ln * 4 + slot] = f2tf32(a_st[i][e]);
            }
        }
        int slab = bkr >> 3, kk = bkr & 7;
#pragma unroll
        for (int i = 0; i < 2; i++)
#pragma unroll
            for (int e = 0; e < 4; e++) {
                int nc = bnc0 + i * 4 + e, nsub = nc >> 3, nn = nc & 7;
                int ln = (nn << 2) | (kk & 3), slot = kk >> 2;
                Bs[0][slab][nsub][ln * 2 + slot] = f2tf32(b_st[i][e]);
            }
    }
    __syncthreads();

    const int NIT = K >> 4;
    for (int it = 0; it < NIT; ++it) {
        const int cur = it & 1;
        if (it + 1 < NIT) {
            int k0 = (it + 1) << 4;
#pragma unroll
            for (int i = 0; i < 2; i++) {
                *(float4*)a_st[i] = *(const float4*)&A[(size_t)(bm + arow + i * 64) * K + k0 + acg];
                *(float4*)b_st[i] = *(const float4*)&Bm[(size_t)(k0 + bkr) * N + bn + bnc0 + i * 4];
            }
        }
        // compute on buffer cur
#pragma unroll
        for (int slab = 0; slab < 2; ++slab) {
            uint4 af[4];
            uint2 bf[4];
#pragma unroll
            for (int m = 0; m < 4; m++)
                af[m] = *(const uint4*)&As[cur][slab][wm * 4 + m][lane * 4];
#pragma unroll
            for (int n = 0; n < 4; n++)
                bf[n] = *(const uint2*)&Bs[cur][slab][wn * 4 + n][lane * 2];
#pragma unroll
            for (int m = 0; m < 4; m++)
#pragma unroll
                for (int n = 0; n < 4; n++)
                    MMA_TF32(acc[m][n], af[m], bf[n]);
        }
        if (it + 1 < NIT) {
            int nxt = cur ^ 1;
#pragma unroll
            for (int i = 0; i < 2; i++) {
                int row = arow + i * 64, msub = row >> 4, r = row & 15;
#pragma unroll
                for (int e = 0; e < 4; e++) {
                    int c = acg + e, slab = c >> 3, cc = c & 7;
                    int ln = ((r & 7) << 2) | (cc & 3);
                    int slot = ((r >> 3) & 1) | ((cc >> 2) << 1);
                    As[nxt][slab][msub][ln * 4 + slot] = f2tf32(a_st[i][e]);
                }
            }
            int slab = bkr >> 3, kk = bkr & 7;
#pragma unroll
            for (int i = 0; i < 2; i++)
#pragma unroll
                for (int e = 0; e < 4; e++) {
                    int nc = bnc0 + i * 4 + e, nsub = nc >> 3, nn = nc & 7;
                    int ln = (nn << 2) | (kk & 3), slot = kk >> 2;
                    Bs[nxt][slab][nsub][ln * 2 + slot] = f2tf32(b_st[i][e]);
                }
        }
        __syncthreads();
    }

    // ---- epilogue
    const int g = lane >> 2, t = lane & 3;
#pragma unroll
    for (int m = 0; m < 4; m++) {
        int row = bm + wm * 64 + m * 16 + g;
#pragma unroll
        for (int n = 0; n < 4; n++) {
            int col = bn + wn * 32 + n * 8 + t * 2;
            float b0 = bias[col], b1 = bias[col + 1];
            float2 v0 = make_float2(acc[m][n][0] + b0, acc[m][n][1] + b1);
            float2 v1 = make_float2(acc[m][n][2] + b0, acc[m][n][3] + b1);
            *(float2*)&C[(size_t)row * N + col]       = v0;
            *(float2*)&C[(size_t)(row + 8) * N + col] = v1;
        }
    }
}

// ---------------- fused masked-softmax attention (fp32, 4x4 reg tiles) -------
// grid (S/64, B*H), 256 threads. Block: 64 q-rows x full head; 64-key chunks.
// Thread (ty=tid>>4, tx=tid&15): rows 4ty..+3, cols 4tx..+3 (keys in GEMM1,
// dh in GEMM2). Dynamic smem: qt/kt/vs/pst, each [64][68] floats.
__global__ __launch_bounds__(256, 3)
void attn_kernel(const int* __restrict__ mask)
{
    extern __shared__ float sm[];
    float* qt  = sm;                 // [k][qrow]
    float* kt  = sm + 64 * 68;       // [k][key]
    float* vs  = sm + 2 * 64 * 68;   // [key][dh]
    float* pst = sm + 3 * 64 * 68;   // [key][qrow]

    const int tid = threadIdx.x;
    const int b  = blockIdx.y >> 4;
    const int h  = blockIdx.y & 15;
    const int q0 = blockIdx.x * 64;
    const int r0 = (tid >> 4) * 4;
    const int c0 = (tid & 15) * 4;

    const int lrow = tid >> 2;          // 0..63
    const int lcb  = (tid & 3) * 16;    // 0,16,32,48

    // Q tile (transposed, scale 1/32 folded in)
    {
        const float* qp = g_qkv + (size_t)(b * SS + q0 + lrow) * QKVN + h * DHH + lcb;
#pragma unroll
        for (int i = 0; i < 4; i++) {
            float4 v = ((const float4*)qp)[i];
            int c = lcb + i * 4;
            qt[(c + 0) * 68 + lrow] = v.x * 0.03125f;
            qt[(c + 1) * 68 + lrow] = v.y * 0.03125f;
            qt[(c + 2) * 68 + lrow] = v.z * 0.03125f;
            qt[(c + 3) * 68 + lrow] = v.w * 0.03125f;
        }
    }

    float m4[4], l4[4], o[4][4];
#pragma unroll
    for (int i = 0; i < 4; i++) {
        m4[i] = -1e30f; l4[i] = 0.f;
#pragma unroll
        for (int j = 0; j < 4; j++) o[i][j] = 0.f;
    }

#pragma unroll 1
    for (int j = 0; j < 16; ++j) {
        __syncthreads();
        {
            const float* kp = g_qkv + (size_t)(b * SS + j * 64 + lrow) * QKVN + 1024 + h * DHH + lcb;
#pragma unroll
            for (int i = 0; i < 4; i++) {
                float4 v = ((const float4*)kp)[i];
                int c = lcb + i * 4;
                kt[(c + 0) * 68 + lrow] = v.x;
                kt[(c + 1) * 68 + lrow] = v.y;
                kt[(c + 2) * 68 + lrow] = v.z;
                kt[(c + 3) * 68 + lrow] = v.w;
            }
            const float* vp = g_qkv + (size_t)(b * SS + j * 64 + lrow) * QKVN + 2048 + h * DHH + lcb;
#pragma unroll
            for (int i = 0; i < 4; i++)
                *(float4*)&vs[lrow * 68 + lcb + i * 4] = ((const float4*)vp)[i];
        }
        __syncthreads();

        // GEMM1: s[4q][4key]
        float s[4][4];
#pragma unroll
        for (int i = 0; i < 4; i++)
#pragma unroll
            for (int jj = 0; jj < 4; jj++) s[i][jj] = 0.f;
#pragma unroll 8
        for (int k = 0; k < 64; ++k) {
            float4 a  = *(const float4*)&qt[k * 68 + r0];
            float4 bb = *(const float4*)&kt[k * 68 + c0];
            s[0][0] += a.x * bb.x; s[0][1] += a.x * bb.y; s[0][2] += a.x * bb.z; s[0][3] += a.x * bb.w;
            s[1][0] += a.y * bb.x; s[1][1] += a.y * bb.y; s[1][2] += a.y * bb.z; s[1][3] += a.y * bb.w;
            s[2][0] += a.z * bb.x; s[2][1] += a.z * bb.y; s[2][2] += a.z * bb.z; s[2][3] += a.z * bb.w;
            s[3][0] += a.w * bb.x; s[3][1] += a.w * bb.y; s[3][2] += a.w * bb.z; s[3][3] += a.w * bb.w;
        }

        // mask (nonzero -> -1e9)
#pragma unroll
        for (int i = 0; i < 4; i++) {
            int4 mk = *(const int4*)(mask + (size_t)b * SS * SS + (size_t)(q0 + r0 + i) * SS + j * 64 + c0);
            if (mk.x) s[i][0] = -1e9f;
            if (mk.y) s[i][1] = -1e9f;
            if (mk.z) s[i][2] = -1e9f;
            if (mk.w) s[i][3] = -1e9f;
        }

        // online softmax per row (16-thread row groups)
        float p[4][4];
#pragma unroll
        for (int i = 0; i < 4; i++) {
            float mx = fmaxf(fmaxf(s[i][0], s[i][1]), fmaxf(s[i][2], s[i][3]));
#pragma unroll
            for (int off = 8; off > 0; off >>= 1)
                mx = fmaxf(mx, __shfl_xor_sync(0xffffffffu, mx, off, 16));
            float mn = fmaxf(m4[i], mx);
            float al = __expf(m4[i] - mn);
            m4[i] = mn;
            float psum = 0.f;
#pragma unroll
            for (int jj = 0; jj < 4; jj++) {
                p[i][jj] = __expf(s[i][jj] - mn);
                psum += p[i][jj];
            }
#pragma unroll
            for (int off = 8; off > 0; off >>= 1)
                psum += __shfl_xor_sync(0xffffffffu, psum, off, 16);
            l4[i] = l4[i] * al + psum;
#pragma unroll
            for (int jj = 0; jj < 4; jj++) o[i][jj] *= al;
        }

        // stage P transposed (writers and readers of these rows share a warp)
#pragma unroll
        for (int jj = 0; jj < 4; jj++) {
            float4 pj = make_float4(p[0][jj], p[1][jj], p[2][jj], p[3][jj]);
            *(float4*)&pst[(c0 + jj) * 68 + r0] = pj;
        }
        __syncwarp();

        // GEMM2: o += P @ V
#pragma unroll 8
        for (int ck = 0; ck < 64; ++ck) {
            float4 pr = *(const float4*)&pst[ck * 68 + r0];
            float4 vv = *(const float4*)&vs[ck * 68 + c0];
            o[0][0] += pr.x * vv.x; o[0][1] += pr.x * vv.y; o[0][2] += pr.x * vv.z; o[0][3] += pr.x * vv.w;
            o[1][0] += pr.y * vv.x; o[1][1] += pr.y * vv.y; o[1][2] += pr.y * vv.z; o[1][3] += pr.y * vv.w;
            o[2][0] += pr.z * vv.x; o[2][1] += pr.z * vv.y; o[2][2] += pr.z * vv.z; o[2][3] += pr.z * vv.w;
            o[3][0] += pr.w * vv.x; o[3][1] += pr.w * vv.y; o[3][2] += pr.w * vv.z; o[3][3] += pr.w * vv.w;
        }
    }

#pragma unroll
    for (int i = 0; i < 4; i++) {
        float inv = 1.f / l4[i];
        float4 ov = make_float4(o[i][0] * inv, o[i][1] * inv, o[i][2] * inv, o[i][3] * inv);
        *(float4*)(g_ctx + (size_t)(b * SS + q0 + r0 + i) * DD + h * DHH + c0) = ov;
    }
}

// ---------------- launch -----------------------------------------------------
extern "C" void kernel_launch(void* const* d_in, const int* in_sizes, int n_in,
                              void* d_out, int out_size)
{
    const float* x  = (const float*)d_in[0];
    const int* mask = (const int*)d_in[1];
    const float* Wq = (const float*)d_in[2];
    const float* bq = (const float*)d_in[3];
    const float* Wk = (const float*)d_in[4];
    const float* bk = (const float*)d_in[5];
    const float* Wv = (const float*)d_in[6];
    const float* bv = (const float*)d_in[7];
    const float* Wo = (const float*)d_in[8];
    const float* bo = (const float*)d_in[9];
    float* out = (float*)d_out;

    void *p_w, *p_b, *p_qkv, *p_ctx;
    cudaGetSymbolAddress(&p_w, g_w);
    cudaGetSymbolAddress(&p_b, g_b);
    cudaGetSymbolAddress(&p_qkv, g_qkv);
    cudaGetSymbolAddress(&p_ctx, g_ctx);

    static int smem_set = 0;
    const int ATTN_SMEM = 4 * 64 * 68 * (int)sizeof(float);   // 69632
    if (!smem_set) {
        cudaFuncSetAttribute(attn_kernel, cudaFuncAttributeMaxDynamicSharedMemorySize, ATTN_SMEM);
        smem_set = 1;
    }

    // 1) pack weights
    pack_w_kernel<<<(KDIM * QKVN + 255) / 256, 256>>>(Wq, bq, Wk, bk, Wv, bv);

    // 2) QKV projection (tf32 tensor cores)
    tf32_gemm_bias<<<dim3(QKVN / 128, MROWS / 128), 256>>>(
        x, (const float*)p_w, (const float*)p_b, (float*)p_qkv, MROWS, QKVN, KDIM);

    // 3) fused masked attention
    attn_kernel<<<dim3(SS / 64, BB * HH), 256, ATTN_SMEM>>>(mask);

    // 4) output projection (tf32 tensor cores)
    tf32_gemm_bias<<<dim3(DD / 128, MROWS / 128), 256>>>(
        (const float*)p_ctx, Wo, bo, out, MROWS, DD, KDIM);
}

// round 4
// speedup vs baseline: 3.9169x; 1.5160x over previous
#include <cuda_runtime.h>
#include <cstdint>

#define BB 8
#define SS 1024
#define DD 1024
#define HH 16
#define DHH 64
#define QKVN 3072
#define MROWS 8192
#define KDIM 1024

// ---------------- scratch ----------------------------------------------------
__device__ float g_w[KDIM * QKVN];
__device__ float g_b[QKVN];
__device__ float g_qkv[(size_t)MROWS * QKVN];
__device__ float g_ctx[(size_t)MROWS * DD];

// ---------------- pack Wq/Wk/Wv [H,D,DH] -> g_w [D][3*H*DH] ------------------
__global__ void pack_w_kernel(const float* __restrict__ Wq, const float* __restrict__ bq,
                              const float* __restrict__ Wk, const float* __restrict__ bk,
                              const float* __restrict__ Wv, const float* __restrict__ bv)
{
    int idx = blockIdx.x * 256 + threadIdx.x;
    if (idx < KDIM * QKVN) {
        int d   = idx / QKVN;
        int col = idx - d * QKVN;
        int which = col >> 10;
        int he  = col & 1023;
        int h   = he >> 6;
        int e   = he & 63;
        const float* W = (which == 0) ? Wq : ((which == 1) ? Wk : Wv);
        g_w[idx] = W[(h * KDIM + d) * DHH + e];
    }
    if (idx < QKVN) {
        int which = idx >> 10;
        int he = idx & 1023;
        const float* bb = (which == 0) ? bq : ((which == 1) ? bk : bv);
        g_b[idx] = bb[he];
    }
}

// ---------------- tf32 helpers ----------------------------------------------
__device__ __forceinline__ unsigned f2tf32(float x) {
    unsigned u;
    asm("cvt.rna.tf32.f32 %0, %1;" : "=r"(u) : "f"(x));
    return u;
}

#define MMA_TF32(c, a, b)                                                     \
    asm volatile("mma.sync.aligned.m16n8k8.row.col.f32.tf32.tf32.f32 "        \
                 "{%0,%1,%2,%3}, {%4,%5,%6,%7}, {%8,%9}, {%0,%1,%2,%3};"      \
                 : "+f"((c)[0]), "+f"((c)[1]), "+f"((c)[2]), "+f"((c)[3])     \
                 : "r"((a).x), "r"((a).y), "r"((a).z), "r"((a).w),            \
                   "r"((b).x), "r"((b).y))

// ---------------- tf32 tensor-core GEMM + bias (unchanged, 91 TF/s) ----------
__global__ __launch_bounds__(256, 2)
void tf32_gemm_bias(const float* __restrict__ A, const float* __restrict__ Bm,
                    const float* __restrict__ bias, float* __restrict__ C,
                    int M, int N, int K)
{
    __shared__ unsigned As[2][2][8][128];
    __shared__ unsigned Bs[2][2][16][66];

    const int tid  = threadIdx.x;
    const int lane = tid & 31;
    const int wid  = tid >> 5;
    const int wm   = wid >> 2;
    const int wn   = wid & 3;
    const int bm   = blockIdx.y * 128;
    const int bn   = blockIdx.x * 128;

    const int arow = tid >> 2;
    const int acg  = (tid & 3) * 4;
    const int bkr  = tid >> 4;
    const int bnc0 = (tid & 15) * 8;

    float acc[4][4][4];
#pragma unroll
    for (int m = 0; m < 4; m++)
#pragma unroll
        for (int n = 0; n < 4; n++)
#pragma unroll
            for (int e = 0; e < 4; e++) acc[m][n][e] = 0.f;

    float a_st[2][4], b_st[2][4];

#pragma unroll
    for (int i = 0; i < 2; i++) {
        *(float4*)a_st[i] = *(const float4*)&A[(size_t)(bm + arow + i * 64) * K + acg];
        *(float4*)b_st[i] = *(const float4*)&Bm[(size_t)(bkr) * N + bn + bnc0 + i * 4];
    }
    {
#pragma unroll
        for (int i = 0; i < 2; i++) {
            int row = arow + i * 64, msub = row >> 4, r = row & 15;
#pragma unroll
            for (int e = 0; e < 4; e++) {
                int c = acg + e, slab = c >> 3, cc = c & 7;
                int ln = ((r & 7) << 2) | (cc & 3);
                int slot = ((r >> 3) & 1) | ((cc >> 2) << 1);
                As[0][slab][msub][ln * 4 + slot] = f2tf32(a_st[i][e]);
            }
        }
        int slab = bkr >> 3, kk = bkr & 7;
#pragma unroll
        for (int i = 0; i < 2; i++)
#pragma unroll
            for (int e = 0; e < 4; e++) {
                int nc = bnc0 + i * 4 + e, nsub = nc >> 3, nn = nc & 7;
                int ln = (nn << 2) | (kk & 3), slot = kk >> 2;
                Bs[0][slab][nsub][ln * 2 + slot] = f2tf32(b_st[i][e]);
            }
    }
    __syncthreads();

    const int NIT = K >> 4;
    for (int it = 0; it < NIT; ++it) {
        const int cur = it & 1;
        if (it + 1 < NIT) {
            int k0 = (it + 1) << 4;
#pragma unroll
            for (int i = 0; i < 2; i++) {
                *(float4*)a_st[i] = *(const float4*)&A[(size_t)(bm + arow + i * 64) * K + k0 + acg];
                *(float4*)b_st[i] = *(const float4*)&Bm[(size_t)(k0 + bkr) * N + bn + bnc0 + i * 4];
            }
        }
#pragma unroll
        for (int slab = 0; slab < 2; ++slab) {
            uint4 af[4];
            uint2 bf[4];
#pragma unroll
            for (int m = 0; m < 4; m++)
                af[m] = *(const uint4*)&As[cur][slab][wm * 4 + m][lane * 4];
#pragma unroll
            for (int n = 0; n < 4; n++)
                bf[n] = *(const uint2*)&Bs[cur][slab][wn * 4 + n][lane * 2];
#pragma unroll
            for (int m = 0; m < 4; m++)
#pragma unroll
                for (int n = 0; n < 4; n++)
                    MMA_TF32(acc[m][n], af[m], bf[n]);
        }
        if (it + 1 < NIT) {
            int nxt = cur ^ 1;
#pragma unroll
            for (int i = 0; i < 2; i++) {
                int row = arow + i * 64, msub = row >> 4, r = row & 15;
#pragma unroll
                for (int e = 0; e < 4; e++) {
                    int c = acg + e, slab = c >> 3, cc = c & 7;
                    int ln = ((r & 7) << 2) | (cc & 3);
                    int slot = ((r >> 3) & 1) | ((cc >> 2) << 1);
                    As[nxt][slab][msub][ln * 4 + slot] = f2tf32(a_st[i][e]);
                }
            }
            int slab = bkr >> 3, kk = bkr & 7;
#pragma unroll
            for (int i = 0; i < 2; i++)
#pragma unroll
                for (int e = 0; e < 4; e++) {
                    int nc = bnc0 + i * 4 + e, nsub = nc >> 3, nn = nc & 7;
                    int ln = (nn << 2) | (kk & 3), slot = kk >> 2;
                    Bs[nxt][slab][nsub][ln * 2 + slot] = f2tf32(b_st[i][e]);
                }
        }
        __syncthreads();
    }

    const int g = lane >> 2, t = lane & 3;
#pragma unroll
    for (int m = 0; m < 4; m++) {
        int row = bm + wm * 64 + m * 16 + g;
#pragma unroll
        for (int n = 0; n < 4; n++) {
            int col = bn + wn * 32 + n * 8 + t * 2;
            float b0 = bias[col], b1 = bias[col + 1];
            float2 v0 = make_float2(acc[m][n][0] + b0, acc[m][n][1] + b1);
            float2 v1 = make_float2(acc[m][n][2] + b0, acc[m][n][3] + b1);
            *(float2*)&C[(size_t)row * N + col]       = v0;
            *(float2*)&C[(size_t)(row + 8) * N + col] = v1;
        }
    }
}

// ---------------- tensor-core flash attention --------------------------------
// grid (S/128, B*H), 256 threads = 8 warps. Warp w: q rows [w*16, w*16+16).
// 16 chunks of 64 keys. All fragments staged fragment-major in smem.
// Smem words: qf[8w][8slab][128] | kf[8slab][8nf][64] | vf[...] | pf[8w][8slab][128]
__global__ __launch_bounds__(256, 2)
void attn_mma_kernel(const int* __restrict__ mask)
{
    extern __shared__ unsigned sm_u[];
    unsigned* qf = sm_u;                   // 8192 words
    unsigned* kf = sm_u + 8192;            // 4096
    unsigned* vf = sm_u + 12288;           // 4096
    unsigned* pf = sm_u + 16384;           // 8192

    const int tid  = threadIdx.x;
    const int lane = tid & 31;
    const int wq   = tid >> 5;
    const int g    = lane >> 2;
    const int t    = lane & 3;
    const int b    = blockIdx.y >> 4;
    const int h    = blockIdx.y & 15;
    const int q0   = blockIdx.x * 128;

    const int lrow = tid >> 2;          // 0..63
    const int lcb  = (tid & 3) * 16;    // 0,16,32,48

    // ---- stage Q (scale 1/32 folded, tf32) into per-warp A-frag layout
#pragma unroll
    for (int i = 0; i < 2; i++) {
        int row = i * 64 + lrow;
        const float* qp = g_qkv + (size_t)(b * SS + q0 + row) * QKVN + h * DHH + lcb;
        int wdst = row >> 4, r = row & 15;
#pragma unroll
        for (int u = 0; u < 4; u++) {
            float4 v = ((const float4*)qp)[u];
            float vv[4] = {v.x, v.y, v.z, v.w};
#pragma unroll
            for (int e = 0; e < 4; e++) {
                int c = lcb + u * 4 + e;
                int slab = c >> 3, cc = c & 7;
                int ln = ((r & 7) << 2) | (cc & 3);
                int slot = ((r >> 3) & 1) | ((cc >> 2) << 1);
                qf[wdst * 1024 + slab * 128 + ln * 4 + slot] = f2tf32(vv[e] * 0.03125f);
            }
        }
    }

    float o[8][4];
#pragma unroll
    for (int nf = 0; nf < 8; nf++)
#pragma unroll
        for (int e = 0; e < 4; e++) o[nf][e] = 0.f;
    float m0 = -1e30f, m1 = -1e30f, l0 = 0.f, l1 = 0.f;

    const size_t mbase = (size_t)b * SS * SS;
    unsigned* pw = pf + wq * 1024;

#pragma unroll 1
    for (int ch = 0; ch < 16; ++ch) {
        __syncthreads();
        // ---- stage K (B-frag for QK^T) and V^T (B-frag for PV)
        {
            const float* kp = g_qkv + (size_t)(b * SS + ch * 64 + lrow) * QKVN + 1024 + h * DHH + lcb;
            const float* vp = kp + 1024;
            int nfK = lrow >> 3, nnK = lrow & 7;       // K: n = key
            int slV = lrow >> 3, kkV = lrow & 7;       // V: k = key
#pragma unroll
            for (int u = 0; u < 4; u++) {
                float4 v = ((const float4*)kp)[u];
                float vv[4] = {v.x, v.y, v.z, v.w};
#pragma unroll
                for (int e = 0; e < 4; e++) {
                    int c = lcb + u * 4 + e;           // dh index = k of GEMM1
                    int slab = c >> 3, kk = c & 7;
                    kf[slab * 512 + nfK * 64 + (((nnK) << 2) | (kk & 3)) * 2 + (kk >> 2)] = f2tf32(vv[e]);
                }
            }
#pragma unroll
            for (int u = 0; u < 4; u++) {
                float4 v = ((const float4*)vp)[u];
                float vv[4] = {v.x, v.y, v.z, v.w};
#pragma unroll
                for (int e = 0; e < 4; e++) {
                    int c = lcb + u * 4 + e;           // dh index = n of GEMM2
                    int nf = c >> 3, nn = c & 7;
                    vf[slV * 512 + nf * 64 + ((nn << 2) | (kkV & 3)) * 2 + (kkV >> 2)] = f2tf32(vv[e]);
                }
            }
        }
        __syncthreads();

        // ---- GEMM1: S[16 q][64 keys]
        float s[8][4];
#pragma unroll
        for (int nf = 0; nf < 8; nf++)
#pragma unroll
            for (int e = 0; e < 4; e++) s[nf][e] = 0.f;
#pragma unroll
        for (int slab = 0; slab < 8; ++slab) {
            uint4 a = *(const uint4*)&qf[wq * 1024 + slab * 128 + lane * 4];
#pragma unroll
            for (int nf = 0; nf < 8; nf++) {
                uint2 bb = *(const uint2*)&kf[slab * 512 + nf * 64 + lane * 2];
                MMA_TF32(s[nf], a, bb);
            }
        }

        // ---- mask (nonzero -> -1e9); rows g and g+8, cols 2t,2t+1 per nfrag
        const int rg = q0 + wq * 16 + g;
        const int kb = ch * 64;
#pragma unroll
        for (int nf = 0; nf < 8; nf++) {
            int col = kb + nf * 8 + 2 * t;
            int2 mk0 = *(const int2*)(mask + mbase + (size_t)rg * SS + col);
            int2 mk1 = *(const int2*)(mask + mbase + (size_t)(rg + 8) * SS + col);
            if (mk0.x) s[nf][0] = -1e9f;
            if (mk0.y) s[nf][1] = -1e9f;
            if (mk1.x) s[nf][2] = -1e9f;
            if (mk1.y) s[nf][3] = -1e9f;
        }

        // ---- online softmax (row stats across the 4-lane quad)
        float mx0 = -1e30f, mx1 = -1e30f;
#pragma unroll
        for (int nf = 0; nf < 8; nf++) {
            mx0 = fmaxf(mx0, fmaxf(s[nf][0], s[nf][1]));
            mx1 = fmaxf(mx1, fmaxf(s[nf][2], s[nf][3]));
        }
        mx0 = fmaxf(mx0, __shfl_xor_sync(0xffffffffu, mx0, 1));
        mx0 = fmaxf(mx0, __shfl_xor_sync(0xffffffffu, mx0, 2));
        mx1 = fmaxf(mx1, __shfl_xor_sync(0xffffffffu, mx1, 1));
        mx1 = fmaxf(mx1, __shfl_xor_sync(0xffffffffu, mx1, 2));
        float mn0 = fmaxf(m0, mx0), mn1 = fmaxf(m1, mx1);
        float a0 = __expf(m0 - mn0), a1 = __expf(m1 - mn1);
        m0 = mn0; m1 = mn1;

        float p[8][4];
        float ps0 = 0.f, ps1 = 0.f;
#pragma unroll
        for (int nf = 0; nf < 8; nf++) {
            p[nf][0] = __expf(s[nf][0] - mn0);
            p[nf][1] = __expf(s[nf][1] - mn0);
            p[nf][2] = __expf(s[nf][2] - mn1);
            p[nf][3] = __expf(s[nf][3] - mn1);
            ps0 += p[nf][0] + p[nf][1];
            ps1 += p[nf][2] + p[nf][3];
        }
        ps0 += __shfl_xor_sync(0xffffffffu, ps0, 1);
        ps0 += __shfl_xor_sync(0xffffffffu, ps0, 2);
        ps1 += __shfl_xor_sync(0xffffffffu, ps1, 1);
        ps1 += __shfl_xor_sync(0xffffffffu, ps1, 2);
        l0 = l0 * a0 + ps0;
        l1 = l1 * a1 + ps1;
#pragma unroll
        for (int nf = 0; nf < 8; nf++) {
            o[nf][0] *= a0; o[nf][1] *= a0;
            o[nf][2] *= a1; o[nf][3] *= a1;
        }

        // ---- P -> smem in A-frag layout (paired rows g/g+8 => STS.64)
        {
            int ln0 = (g << 2) | ((2 * t) & 3);
            int ln1 = (g << 2) | ((2 * t + 1) & 3);
            int sl  = (t >> 1) << 1;
#pragma unroll
            for (int nf = 0; nf < 8; nf++) {
                uint2 w0 = make_uint2(f2tf32(p[nf][0]), f2tf32(p[nf][2]));
                uint2 w1 = make_uint2(f2tf32(p[nf][1]), f2tf32(p[nf][3]));
                *(uint2*)&pw[nf * 128 + ln0 * 4 + sl] = w0;
                *(uint2*)&pw[nf * 128 + ln1 * 4 + sl] = w1;
            }
        }
        __syncwarp();

        // ---- GEMM2: O += P @ V
#pragma unroll
        for (int slab = 0; slab < 8; ++slab) {
            uint4 a = *(const uint4*)&pw[slab * 128 + lane * 4];
#pragma unroll
            for (int nf = 0; nf < 8; nf++) {
                uint2 bb = *(const uint2*)&vf[slab * 512 + nf * 64 + lane * 2];
                MMA_TF32(o[nf], a, bb);
            }
        }
    }

    // ---- epilogue
    float i0 = 1.f / l0, i1 = 1.f / l1;
    int row0 = q0 + wq * 16 + g;
#pragma unroll
    for (int nf = 0; nf < 8; nf++) {
        int col = h * DHH + nf * 8 + 2 * t;
        float2 v0 = make_float2(o[nf][0] * i0, o[nf][1] * i0);
        float2 v1 = make_float2(o[nf][2] * i1, o[nf][3] * i1);
        *(float2*)(g_ctx + (size_t)(b * SS + row0) * DD + col)     = v0;
        *(float2*)(g_ctx + (size_t)(b * SS + row0 + 8) * DD + col) = v1;
    }
}

// ---------------- launch -----------------------------------------------------
extern "C" void kernel_launch(void* const* d_in, const int* in_sizes, int n_in,
                              void* d_out, int out_size)
{
    const float* x  = (const float*)d_in[0];
    const int* mask = (const int*)d_in[1];
    const float* Wq = (const float*)d_in[2];
    const float* bq = (const float*)d_in[3];
    const float* Wk = (const float*)d_in[4];
    const float* bk = (const float*)d_in[5];
    const float* Wv = (const float*)d_in[6];
    const float* bv = (const float*)d_in[7];
    const float* Wo = (const float*)d_in[8];
    const float* bo = (const float*)d_in[9];
    float* out = (float*)d_out;

    void *p_w, *p_b, *p_qkv, *p_ctx;
    cudaGetSymbolAddress(&p_w, g_w);
    cudaGetSymbolAddress(&p_b, g_b);
    cudaGetSymbolAddress(&p_qkv, g_qkv);
    cudaGetSymbolAddress(&p_ctx, g_ctx);

    const int ATTN_SMEM = 24576 * (int)sizeof(unsigned);   // 98304 B
    static int smem_set = 0;
    if (!smem_set) {
        cudaFuncSetAttribute(attn_mma_kernel, cudaFuncAttributeMaxDynamicSharedMemorySize, ATTN_SMEM);
        smem_set = 1;
    }

    pack_w_kernel<<<(KDIM * QKVN + 255) / 256, 256>>>(Wq, bq, Wk, bk, Wv, bv);

    tf32_gemm_bias<<<dim3(QKVN / 128, MROWS / 128), 256>>>(
        x, (const float*)p_w, (const float*)p_b, (float*)p_qkv, MROWS, QKVN, KDIM);

    attn_mma_kernel<<<dim3(SS / 128, BB * HH), 256, ATTN_SMEM>>>(mask);

    tf32_gemm_bias<<<dim3(DD / 128, MROWS / 128), 256>>>(
        (const float*)p_ctx, Wo, bo, out, MROWS, DD, KDIM);
}

// round 5
// speedup vs baseline: 4.3127x; 1.1011x over previous
#include <cuda_runtime.h>
#include <cstdint>

#define BB 8
#define SS 1024
#define DD 1024
#define HH 16
#define DHH 64
#define QKVN 3072
#define MROWS 8192
#define KDIM 1024

// ---------------- scratch ----------------------------------------------------
__device__ float g_w[KDIM * QKVN];
__device__ float g_b[QKVN];
__device__ float g_qkv[(size_t)MROWS * QKVN];
__device__ float g_ctx[(size_t)MROWS * DD];

// ---------------- pack Wq/Wk/Wv [H,D,DH] -> g_w [D][3*H*DH] ------------------
__global__ void pack_w_kernel(const float* __restrict__ Wq, const float* __restrict__ bq,
                              const float* __restrict__ Wk, const float* __restrict__ bk,
                              const float* __restrict__ Wv, const float* __restrict__ bv)
{
    int idx = blockIdx.x * 256 + threadIdx.x;
    if (idx < KDIM * QKVN) {
        int d   = idx / QKVN;
        int col = idx - d * QKVN;
        int which = col >> 10;
        int he  = col & 1023;
        int h   = he >> 6;
        int e   = he & 63;
        const float* W = (which == 0) ? Wq : ((which == 1) ? Wk : Wv);
        g_w[idx] = W[(h * KDIM + d) * DHH + e];
    }
    if (idx < QKVN) {
        int which = idx >> 10;
        int he = idx & 1023;
        const float* bb = (which == 0) ? bq : ((which == 1) ? bk : bv);
        g_b[idx] = bb[he];
    }
}

// ---------------- tf32 helpers ----------------------------------------------
__device__ __forceinline__ unsigned f2tf32(float x) {
    unsigned u;
    asm("cvt.rna.tf32.f32 %0, %1;" : "=r"(u) : "f"(x));
    return u;
}

#define MMA_TF32(c, a, b)                                                     \
    asm volatile("mma.sync.aligned.m16n8k8.row.col.f32.tf32.tf32.f32 "        \
                 "{%0,%1,%2,%3}, {%4,%5,%6,%7}, {%8,%9}, {%0,%1,%2,%3};"      \
                 : "+f"((c)[0]), "+f"((c)[1]), "+f"((c)[2]), "+f"((c)[3])     \
                 : "r"((a).x), "r"((a).y), "r"((a).z), "r"((a).w),            \
                   "r"((b).x), "r"((b).y))

// ---------------- tf32 GEMM v2: 128x256 block, 64x64 warp tiles --------------
// A smem: frag-major [slab][msub][slot][lane] with bank rotation rot=slab*4+slot
//   -> A STS.128 conflict-free, frag loads 4x LDS.32 conflict-free.
// B smem: natural [k][n] with XOR group-swizzle (n>>2)^(k&7)
//   -> B STS.128 conflict-free, frag loads 2x LDS.32 conflict-free.
__global__ __launch_bounds__(256, 1)
void tf32_gemm_bias(const float* __restrict__ A, const float* __restrict__ Bm,
                    const float* __restrict__ bias, float* __restrict__ C,
                    int M, int N, int K)
{
    __shared__ unsigned As[2][2048];   // 2 slabs * 8 msub * 4 slot * 32 lanes
    __shared__ unsigned Bs[2][4096];   // 16 k * 256 n (swizzled)

    const int tid  = threadIdx.x;
    const int lane = tid & 31;
    const int wid  = tid >> 5;
    const int wm   = wid >> 2;          // 0..1
    const int wn   = wid & 3;           // 0..3
    const int bm   = blockIdx.y * 128;
    const int bn   = blockIdx.x * 256;
    const int g    = lane >> 2;
    const int t    = lane & 3;

    // A ldg/sts mapping: thread -> rows {arow, arow+64}, k cols acg..acg+3
    const int arow = tid >> 2;          // 0..63
    const int acg  = (tid & 3) * 4;     // 0,4,8,12
    const int asl  = acg >> 3;
    const int ac4  = (acg >> 2) & 1;
    // precompute A store word offsets (k-iter invariant)
    int a_off[2];
#pragma unroll
    for (int i = 0; i < 2; i++) {
        int row = arow + 64 * i;
        int msub = row >> 4, r = row & 15, rb = r & 7, rhi = r >> 3;
        int slot = rhi | (ac4 << 1);
        int rot  = asl * 4 + slot;
        a_off[i] = ((asl * 8 + msub) * 4 + slot) * 32 + (((rb + rot) & 7) << 2);
    }
    // B ldg/sts mapping: thread -> k row bkr, 4 float4 groups (tid&15)+16u
    const int bkr = tid >> 4;           // 0..15
    int b_off[4];
#pragma unroll
    for (int u = 0; u < 4; u++) {
        int grp = (tid & 15) + 16 * u;
        b_off[u] = bkr * 256 + ((grp ^ (bkr & 7)) & 63) * 4;
    }

    float acc[4][8][4];
#pragma unroll
    for (int m = 0; m < 4; m++)
#pragma unroll
        for (int nf = 0; nf < 8; nf++)
#pragma unroll
            for (int e = 0; e < 4; e++) acc[m][nf][e] = 0.f;

    float a_ld[2][4], b_ld[4][4];

    const float* Abase = A + (size_t)(bm + arow) * K + acg;
    const float* Bbase = Bm + (size_t)bkr * N + bn + (tid & 15) * 4;

    // ---- first tile LDG
#pragma unroll
    for (int i = 0; i < 2; i++)
        *(float4*)a_ld[i] = *(const float4*)(Abase + (size_t)(64 * i) * K);
#pragma unroll
    for (int u = 0; u < 4; u++)
        *(float4*)b_ld[u] = *(const float4*)(Bbase + 64 * u);
    // ---- first tile STS
#pragma unroll
    for (int i = 0; i < 2; i++) {
        uint4 w = make_uint4(f2tf32(a_ld[i][0]), f2tf32(a_ld[i][1]),
                             f2tf32(a_ld[i][2]), f2tf32(a_ld[i][3]));
        *(uint4*)&As[0][a_off[i]] = w;
    }
#pragma unroll
    for (int u = 0; u < 4; u++) {
        uint4 w = make_uint4(f2tf32(b_ld[u][0]), f2tf32(b_ld[u][1]),
                             f2tf32(b_ld[u][2]), f2tf32(b_ld[u][3]));
        *(uint4*)&Bs[0][b_off[u]] = w;
    }
    __syncthreads();

    const int NIT = K >> 4;
    const int grpbase = wn * 16 + (g >> 2);   // B group base (n>>2 without nf)
    const int g3 = g & 3;

    for (int it = 0; it < NIT; ++it) {
        const int cur = it & 1;
        if (it + 1 < NIT) {
            int k0 = (it + 1) << 4;
#pragma unroll
            for (int i = 0; i < 2; i++)
                *(float4*)a_ld[i] = *(const float4*)(Abase + (size_t)(64 * i) * K + k0);
#pragma unroll
            for (int u = 0; u < 4; u++)
                *(float4*)b_ld[u] = *(const float4*)(Bbase + (size_t)k0 * N + 64 * u);
        }

#pragma unroll
        for (int sl = 0; sl < 2; ++sl) {
            // A fragments: 4x LDS.32 each, bank-rotated layout
            uint4 af[4];
#pragma unroll
            for (int m = 0; m < 4; m++) {
                int base = ((sl * 8 + wm * 4 + m) * 4) * 32;
                af[m].x = As[cur][base          + (((g + sl * 4 + 0) & 7) << 2) + t];
                af[m].y = As[cur][base + 1 * 32 + (((g + sl * 4 + 1) & 7) << 2) + t];
                af[m].z = As[cur][base + 2 * 32 + (((g + sl * 4 + 2) & 7) << 2) + t];
                af[m].w = As[cur][base + 3 * 32 + (((g + sl * 4 + 3) & 7) << 2) + t];
            }
            // B fragments: 2x LDS.32 each, XOR-swizzled layout
            uint2 bf[8];
            int k0r = (sl * 8 + t) * 256;
            int k1r = (sl * 8 + t + 4) * 256;
#pragma unroll
            for (int nf = 0; nf < 8; nf++) {
                int grp = grpbase + nf * 2;
                bf[nf].x = Bs[cur][k0r + ((grp ^ t) & 63) * 4 + g3];
                bf[nf].y = Bs[cur][k1r + ((grp ^ (t + 4)) & 63) * 4 + g3];
            }
#pragma unroll
            for (int m = 0; m < 4; m++)
#pragma unroll
                for (int nf = 0; nf < 8; nf++)
                    MMA_TF32(acc[m][nf], af[m], bf[nf]);
        }

        if (it + 1 < NIT) {
            int nxt = cur ^ 1;
#pragma unroll
            for (int i = 0; i < 2; i++) {
                uint4 w = make_uint4(f2tf32(a_ld[i][0]), f2tf32(a_ld[i][1]),
                                     f2tf32(a_ld[i][2]), f2tf32(a_ld[i][3]));
                *(uint4*)&As[nxt][a_off[i]] = w;
            }
#pragma unroll
            for (int u = 0; u < 4; u++) {
                uint4 w = make_uint4(f2tf32(b_ld[u][0]), f2tf32(b_ld[u][1]),
                                     f2tf32(b_ld[u][2]), f2tf32(b_ld[u][3]));
                *(uint4*)&Bs[nxt][b_off[u]] = w;
            }
        }
        __syncthreads();
    }

    // ---- epilogue
#pragma unroll
    for (int m = 0; m < 4; m++) {
        int row = bm + wm * 64 + m * 16 + g;
#pragma unroll
        for (int nf = 0; nf < 8; nf++) {
            int col = bn + wn * 64 + nf * 8 + 2 * t;
            float b0 = bias[col], b1 = bias[col + 1];
            float2 v0 = make_float2(acc[m][nf][0] + b0, acc[m][nf][1] + b1);
            float2 v1 = make_float2(acc[m][nf][2] + b0, acc[m][nf][3] + b1);
            *(float2*)&C[(size_t)row * N + col]       = v0;
            *(float2*)&C[(size_t)(row + 8) * N + col] = v1;
        }
    }
}

// ---------------- tensor-core flash attention (unchanged from R4) ------------
__global__ __launch_bounds__(256, 2)
void attn_mma_kernel(const int* __restrict__ mask)
{
    extern __shared__ unsigned sm_u[];
    unsigned* qf = sm_u;
    unsigned* kf = sm_u + 8192;
    unsigned* vf = sm_u + 12288;
    unsigned* pf = sm_u + 16384;

    const int tid  = threadIdx.x;
    const int lane = tid & 31;
    const int wq   = tid >> 5;
    const int g    = lane >> 2;
    const int t    = lane & 3;
    const int b    = blockIdx.y >> 4;
    const int h    = blockIdx.y & 15;
    const int q0   = blockIdx.x * 128;

    const int lrow = tid >> 2;
    const int lcb  = (tid & 3) * 16;

#pragma unroll
    for (int i = 0; i < 2; i++) {
        int row = i * 64 + lrow;
        const float* qp = g_qkv + (size_t)(b * SS + q0 + row) * QKVN + h * DHH + lcb;
        int wdst = row >> 4, r = row & 15;
#pragma unroll
        for (int u = 0; u < 4; u++) {
            float4 v = ((const float4*)qp)[u];
            float vv[4] = {v.x, v.y, v.z, v.w};
#pragma unroll
            for (int e = 0; e < 4; e++) {
                int c = lcb + u * 4 + e;
                int slab = c >> 3, cc = c & 7;
                int ln = ((r & 7) << 2) | (cc & 3);
                int slot = ((r >> 3) & 1) | ((cc >> 2) << 1);
                qf[wdst * 1024 + slab * 128 + ln * 4 + slot] = f2tf32(vv[e] * 0.03125f);
            }
        }
    }

    float o[8][4];
#pragma unroll
    for (int nf = 0; nf < 8; nf++)
#pragma unroll
        for (int e = 0; e < 4; e++) o[nf][e] = 0.f;
    float m0 = -1e30f, m1 = -1e30f, l0 = 0.f, l1 = 0.f;

    const size_t mbase = (size_t)b * SS * SS;
    unsigned* pw = pf + wq * 1024;

#pragma unroll 1
    for (int ch = 0; ch < 16; ++ch) {
        __syncthreads();
        {
            const float* kp = g_qkv + (size_t)(b * SS + ch * 64 + lrow) * QKVN + 1024 + h * DHH + lcb;
            const float* vp = kp + 1024;
            int nfK = lrow >> 3, nnK = lrow & 7;
            int slV = lrow >> 3, kkV = lrow & 7;
#pragma unroll
            for (int u = 0; u < 4; u++) {
                float4 v = ((const float4*)kp)[u];
                float vv[4] = {v.x, v.y, v.z, v.w};
#pragma unroll
                for (int e = 0; e < 4; e++) {
                    int c = lcb + u * 4 + e;
                    int slab = c >> 3, kk = c & 7;
                    kf[slab * 512 + nfK * 64 + (((nnK) << 2) | (kk & 3)) * 2 + (kk >> 2)] = f2tf32(vv[e]);
                }
            }
#pragma unroll
            for (int u = 0; u < 4; u++) {
                float4 v = ((const float4*)vp)[u];
                float vv[4] = {v.x, v.y, v.z, v.w};
#pragma unroll
                for (int e = 0; e < 4; e++) {
                    int c = lcb + u * 4 + e;
                    int nf = c >> 3, nn = c & 7;
                    vf[slV * 512 + nf * 64 + ((nn << 2) | (kkV & 3)) * 2 + (kkV >> 2)] = f2tf32(vv[e]);
                }
            }
        }
        __syncthreads();

        float s[8][4];
#pragma unroll
        for (int nf = 0; nf < 8; nf++)
#pragma unroll
            for (int e = 0; e < 4; e++) s[nf][e] = 0.f;
#pragma unroll
        for (int slab = 0; slab < 8; ++slab) {
            uint4 a = *(const uint4*)&qf[wq * 1024 + slab * 128 + lane * 4];
#pragma unroll
            for (int nf = 0; nf < 8; nf++) {
                uint2 bb = *(const uint2*)&kf[slab * 512 + nf * 64 + lane * 2];
                MMA_TF32(s[nf], a, bb);
            }
        }

        const int rg = q0 + wq * 16 + g;
        const int kb = ch * 64;
#pragma unroll
        for (int nf = 0; nf < 8; nf++) {
            int col = kb + nf * 8 + 2 * t;
            int2 mk0 = *(const int2*)(mask + mbase + (size_t)rg * SS + col);
            int2 mk1 = *(const int2*)(mask + mbase + (size_t)(rg + 8) * SS + col);
            if (mk0.x) s[nf][0] = -1e9f;
            if (mk0.y) s[nf][1] = -1e9f;
            if (mk1.x) s[nf][2] = -1e9f;
            if (mk1.y) s[nf][3] = -1e9f;
        }

        float mx0 = -1e30f, mx1 = -1e30f;
#pragma unroll
        for (int nf = 0; nf < 8; nf++) {
            mx0 = fmaxf(mx0, fmaxf(s[nf][0], s[nf][1]));
            mx1 = fmaxf(mx1, fmaxf(s[nf][2], s[nf][3]));
        }
        mx0 = fmaxf(mx0, __shfl_xor_sync(0xffffffffu, mx0, 1));
        mx0 = fmaxf(mx0, __shfl_xor_sync(0xffffffffu, mx0, 2));
        mx1 = fmaxf(mx1, __shfl_xor_sync(0xffffffffu, mx1, 1));
        mx1 = fmaxf(mx1, __shfl_xor_sync(0xffffffffu, mx1, 2));
        float mn0 = fmaxf(m0, mx0), mn1 = fmaxf(m1, mx1);
        float a0 = __expf(m0 - mn0), a1 = __expf(m1 - mn1);
        m0 = mn0; m1 = mn1;

        float p[8][4];
        float ps0 = 0.f, ps1 = 0.f;
#pragma unroll
        for (int nf = 0; nf < 8; nf++) {
            p[nf][0] = __expf(s[nf][0] - mn0);
            p[nf][1] = __expf(s[nf][1] - mn0);
            p[nf][2] = __expf(s[nf][2] - mn1);
            p[nf][3] = __expf(s[nf][3] - mn1);
            ps0 += p[nf][0] + p[nf][1];
            ps1 += p[nf][2] + p[nf][3];
        }
        ps0 += __shfl_xor_sync(0xffffffffu, ps0, 1);
        ps0 += __shfl_xor_sync(0xffffffffu, ps0, 2);
        ps1 += __shfl_xor_sync(0xffffffffu, ps1, 1);
        ps1 += __shfl_xor_sync(0xffffffffu, ps1, 2);
        l0 = l0 * a0 + ps0;
        l1 = l1 * a1 + ps1;
#pragma unroll
        for (int nf = 0; nf < 8; nf++) {
            o[nf][0] *= a0; o[nf][1] *= a0;
            o[nf][2] *= a1; o[nf][3] *= a1;
        }

        {
            int ln0 = (g << 2) | ((2 * t) & 3);
            int ln1 = (g << 2) | ((2 * t + 1) & 3);
            int sl  = (t >> 1) << 1;
#pragma unroll
            for (int nf = 0; nf < 8; nf++) {
                uint2 w0 = make_uint2(f2tf32(p[nf][0]), f2tf32(p[nf][2]));
                uint2 w1 = make_uint2(f2tf32(p[nf][1]), f2tf32(p[nf][3]));
                *(uint2*)&pw[nf * 128 + ln0 * 4 + sl] = w0;
                *(uint2*)&pw[nf * 128 + ln1 * 4 + sl] = w1;
            }
        }
        __syncwarp();

#pragma unroll
        for (int slab = 0; slab < 8; ++slab) {
            uint4 a = *(const uint4*)&pw[slab * 128 + lane * 4];
#pragma unroll
            for (int nf = 0; nf < 8; nf++) {
                uint2 bb = *(const uint2*)&vf[slab * 512 + nf * 64 + lane * 2];
                MMA_TF32(o[nf], a, bb);
            }
        }
    }

    float i0 = 1.f / l0, i1 = 1.f / l1;
    int row0 = q0 + wq * 16 + g;
#pragma unroll
    for (int nf = 0; nf < 8; nf++) {
        int col = h * DHH + nf * 8 + 2 * t;
        float2 v0 = make_float2(o[nf][0] * i0, o[nf][1] * i0);
        float2 v1 = make_float2(o[nf][2] * i1, o[nf][3] * i1);
        *(float2*)(g_ctx + (size_t)(b * SS + row0) * DD + col)     = v0;
        *(float2*)(g_ctx + (size_t)(b * SS + row0 + 8) * DD + col) = v1;
    }
}

// ---------------- launch -----------------------------------------------------
extern "C" void kernel_launch(void* const* d_in, const int* in_sizes, int n_in,
                              void* d_out, int out_size)
{
    const float* x  = (const float*)d_in[0];
    const int* mask = (const int*)d_in[1];
    const float* Wq = (const float*)d_in[2];
    const float* bq = (const float*)d_in[3];
    const float* Wk = (const float*)d_in[4];
    const float* bk = (const float*)d_in[5];
    const float* Wv = (const float*)d_in[6];
    const float* bv = (const float*)d_in[7];
    const float* Wo = (const float*)d_in[8];
    const float* bo = (const float*)d_in[9];
    float* out = (float*)d_out;

    void *p_w, *p_b, *p_qkv, *p_ctx;
    cudaGetSymbolAddress(&p_w, g_w);
    cudaGetSymbolAddress(&p_b, g_b);
    cudaGetSymbolAddress(&p_qkv, g_qkv);
    cudaGetSymbolAddress(&p_ctx, g_ctx);

    const int ATTN_SMEM = 24576 * (int)sizeof(unsigned);   // 98304 B
    static int smem_set = 0;
    if (!smem_set) {
        cudaFuncSetAttribute(attn_mma_kernel, cudaFuncAttributeMaxDynamicSharedMemorySize, ATTN_SMEM);
        smem_set = 1;
    }

    pack_w_kernel<<<(KDIM * QKVN + 255) / 256, 256>>>(Wq, bq, Wk, bk, Wv, bv);

    // QKV projection: [8192x1024] @ [1024x3072]; N tiles of 256
    tf32_gemm_bias<<<dim3(QKVN / 256, MROWS / 128), 256>>>(
        x, (const float*)p_w, (const float*)p_b, (float*)p_qkv, MROWS, QKVN, KDIM);

    attn_mma_kernel<<<dim3(SS / 128, BB * HH), 256, ATTN_SMEM>>>(mask);

    // output projection: [8192x1024] @ [1024x1024]
    tf32_gemm_bias<<<dim3(DD / 256, MROWS / 128), 256>>>(
        (const float*)p_ctx, Wo, bo, out, MROWS, DD, KDIM);
}

// round 8
// speedup vs baseline: 4.8677x; 1.1287x over previous
#include <cuda_runtime.h>
#include <cstdint>

#define BB 8
#define SS 1024
#define DD 1024
#define HH 16
#define DHH 64
#define QKVN 3072
#define MROWS 8192
#define KDIM 1024

// ---------------- scratch ----------------------------------------------------
__device__ float g_w[KDIM * QKVN];                 // packed QKV weights (tf32-rounded)
__device__ float g_b[QKVN];
__device__ float g_qkv[(size_t)MROWS * QKVN];
__device__ float g_ctx[(size_t)MROWS * DD];        // tf32-rounded by attn epilogue
__device__ float g_xt[(size_t)MROWS * KDIM];       // tf32-rounded inputs
__device__ float g_wo[KDIM * DD];                  // tf32-rounded Wo

// ---------------- tf32 helpers ----------------------------------------------
__device__ __forceinline__ unsigned f2tf32(float x) {
    unsigned u;
    asm("cvt.rna.tf32.f32 %0, %1;" : "=r"(u) : "f"(x));
    return u;
}

#define MMA_TF32(c, a, b)                                                     \
    asm volatile("mma.sync.aligned.m16n8k8.row.col.f32.tf32.tf32.f32 "        \
                 "{%0,%1,%2,%3}, {%4,%5,%6,%7}, {%8,%9}, {%0,%1,%2,%3};"      \
                 : "+f"((c)[0]), "+f"((c)[1]), "+f"((c)[2]), "+f"((c)[3])     \
                 : "r"((a).x), "r"((a).y), "r"((a).z), "r"((a).w),            \
                   "r"((b).x), "r"((b).y))

#define CPA16(dst, src)                                                       \
    asm volatile("cp.async.cg.shared.global [%0], [%1], 16;"                  \
                 :: "r"(dst), "l"(__cvta_generic_to_global(src)))
#define CP_COMMIT() asm volatile("cp.async.commit_group;")
#define CP_WAIT2()  asm volatile("cp.async.wait_group 2;")

// ---------------- pack Wq/Wk/Wv [H,D,DH] -> g_w [D][3*H*DH] (tf32) -----------
__global__ void pack_w_kernel(const float* __restrict__ Wq, const float* __restrict__ bq,
                              const float* __restrict__ Wk, const float* __restrict__ bk,
                              const float* __restrict__ Wv, const float* __restrict__ bv)
{
    int idx = blockIdx.x * 256 + threadIdx.x;
    if (idx < KDIM * QKVN) {
        int d   = idx / QKVN;
        int col = idx - d * QKVN;
        int which = col >> 10;
        int he  = col & 1023;
        int h   = he >> 6;
        int e   = he & 63;
        const float* W = (which == 0) ? Wq : ((which == 1) ? Wk : Wv);
        g_w[idx] = __uint_as_float(f2tf32(W[(h * KDIM + d) * DHH + e]));
    }
    if (idx < QKVN) {
        int which = idx >> 10;
        int he = idx & 1023;
        const float* bb = (which == 0) ? bq : ((which == 1) ? bk : bv);
        g_b[idx] = bb[he];
    }
}

// ---------------- elementwise tf32 rounding ----------------------------------
__global__ void round_tf32_kernel(const float4* __restrict__ in, float4* __restrict__ out, int n4)
{
    int i = blockIdx.x * 256 + threadIdx.x;
    if (i < n4) {
        float4 v = in[i];
        v.x = __uint_as_float(f2tf32(v.x));
        v.y = __uint_as_float(f2tf32(v.y));
        v.z = __uint_as_float(f2tf32(v.z));
        v.w = __uint_as_float(f2tf32(v.w));
        out[i] = v;
    }
}

// ---------------- tf32 GEMM v4: cp.async 4-stage, 128x256, 64x64 warps -------
// Inputs MUST be tf32-rounded already. A smem [128][16] chunk-swz (row>>1)&3,
// B smem [16][256] chunk-swz (2k)&7. Stage = 6144 words (24KB), 4 stages.
__global__ __launch_bounds__(256, 1)
void tf32_gemm_bias(const float* __restrict__ A, const float* __restrict__ Bm,
                    const float* __restrict__ bias, float* __restrict__ C,
                    int M, int N, int K)
{
    extern __shared__ unsigned S[];   // 4 * 6144 words = 96KB

    const int tid  = threadIdx.x;
    const int lane = tid & 31;
    const int wid  = tid >> 5;
    const int wm   = wid >> 2;          // 0..1
    const int wn   = wid & 3;           // 0..3
    const int bm   = blockIdx.y * 128;
    const int bn   = blockIdx.x * 256;
    const int g    = lane >> 2;
    const int t    = lane & 3;

    unsigned sbase;
    asm("{ .reg .u64 x0; cvta.to.shared.u64 x0, %1; cvt.u32.u64 %0, x0; }"
        : "=r"(sbase) : "l"(S));

    // ---- cp.async mappings
    const int arow = tid >> 2;          // 0..63 (and +64)
    const int ac   = tid & 3;           // A k-chunk
    const int swA  = (arow >> 1) & 3;
    const float* Asrc = A + (size_t)(bm + arow) * K + 4 * ac;
    const unsigned adst0 = sbase + (unsigned)(arow * 16 + ((ac ^ swA) & 3) * 4) * 4;
    const unsigned adst1 = adst0 + 64 * 16 * 4;

    const int kb = tid >> 4;            // 0..15
    const int bc = tid & 15;
    const int sB = (2 * kb) & 7;
    const float* Bsrc = Bm + (size_t)kb * N + bn + 4 * bc;
    unsigned bdst[4];
#pragma unroll
    for (int u = 0; u < 4; u++)
        bdst[u] = sbase + (unsigned)(2048 + kb * 256 + (((bc + 16 * u) ^ sB) & 63) * 4) * 4;

#define GEMM_ISSUE(it, stg) do {                                               \
        unsigned off_ = (unsigned)(stg) * 24576u;                              \
        const float* as_ = Asrc + (size_t)(it) * 16;                           \
        CPA16(adst0 + off_, as_);                                              \
        CPA16(adst1 + off_, as_ + (size_t)64 * K);                             \
        const float* bs_ = Bsrc + (size_t)(it) * 16 * N;                       \
        CPA16(bdst[0] + off_, bs_);                                            \
        CPA16(bdst[1] + off_, bs_ + 64);                                       \
        CPA16(bdst[2] + off_, bs_ + 128);                                      \
        CPA16(bdst[3] + off_, bs_ + 192);                                      \
    } while (0)

    float acc[4][8][4];
#pragma unroll
    for (int m = 0; m < 4; m++)
#pragma unroll
        for (int nf = 0; nf < 8; nf++)
#pragma unroll
            for (int e = 0; e < 4; e++) acc[m][nf][e] = 0.f;

    GEMM_ISSUE(0, 0); CP_COMMIT();
    GEMM_ISSUE(1, 1); CP_COMMIT();
    GEMM_ISSUE(2, 2); CP_COMMIT();

    const int NIT = K >> 4;
    const int swa = (g >> 1) & 3;

    for (int it = 0; it < NIT; ++it) {
        CP_WAIT2();
        __syncthreads();
        if (it + 3 < NIT) GEMM_ISSUE(it + 3, (it + 3) & 3);
        CP_COMMIT();

        const unsigned* Sa = S + (it & 3) * 6144;
        const unsigned* Sb = Sa + 2048;

#pragma unroll
        for (int sl = 0; sl < 2; ++sl) {
            uint4 af[4];
            const int cx = ((2 * sl) ^ swa) << 2;
            const int cz = ((2 * sl + 1) ^ swa) << 2;
#pragma unroll
            for (int m = 0; m < 4; m++) {
                int rb = (wm * 64 + m * 16 + g) * 16 + t;
                af[m].x = Sa[rb + cx];
                af[m].y = Sa[rb + 128 + cx];
                af[m].z = Sa[rb + cz];
                af[m].w = Sa[rb + 128 + cz];
            }
            uint2 bf[8];
            const int r0 = (sl * 8 + t) * 256 + (g & 3);
            const int r1 = r0 + 4 * 256;
#pragma unroll
            for (int nf = 0; nf < 8; nf++) {
                int c2 = ((wn * 16 + nf * 2 + (g >> 2)) ^ (2 * t)) & 63;
                bf[nf].x = Sb[r0 + c2 * 4];
                bf[nf].y = Sb[r1 + c2 * 4];
            }
#pragma unroll
            for (int m = 0; m < 4; m++)
#pragma unroll
                for (int nf = 0; nf < 8; nf++)
                    MMA_TF32(acc[m][nf], af[m], bf[nf]);
        }
    }

    // ---- epilogue
#pragma unroll
    for (int m = 0; m < 4; m++) {
        int row = bm + wm * 64 + m * 16 + g;
#pragma unroll
        for (int nf = 0; nf < 8; nf++) {
            int col = bn + wn * 64 + nf * 8 + 2 * t;
            float b0 = bias[col], b1 = bias[col + 1];
            float2 v0 = make_float2(acc[m][nf][0] + b0, acc[m][nf][1] + b1);
            float2 v1 = make_float2(acc[m][nf][2] + b0, acc[m][nf][3] + b1);
            *(float2*)&C[(size_t)row * N + col]       = v0;
            *(float2*)&C[(size_t)(row + 8) * N + col] = v1;
        }
    }
#undef GEMM_ISSUE
}

// ---------------- tensor-core flash attention (R4/R5, tf32-rounded output) ---
__global__ __launch_bounds__(256, 2)
void attn_mma_kernel(const int* __restrict__ mask)
{
    extern __shared__ unsigned sm_u[];
    unsigned* qf = sm_u;
    unsigned* kf = sm_u + 8192;
    unsigned* vf = sm_u + 12288;
    unsigned* pf = sm_u + 16384;

    const int tid  = threadIdx.x;
    const int lane = tid & 31;
    const int wq   = tid >> 5;
    const int g    = lane >> 2;
    const int t    = lane & 3;
    const int b    = blockIdx.y >> 4;
    const int h    = blockIdx.y & 15;
    const int q0   = blockIdx.x * 128;

    const int lrow = tid >> 2;
    const int lcb  = (tid & 3) * 16;

#pragma unroll
    for (int i = 0; i < 2; i++) {
        int row = i * 64 + lrow;
        const float* qp = g_qkv + (size_t)(b * SS + q0 + row) * QKVN + h * DHH + lcb;
        int wdst = row >> 4, r = row & 15;
#pragma unroll
        for (int u = 0; u < 4; u++) {
            float4 v = ((const float4*)qp)[u];
            float vv[4] = {v.x, v.y, v.z, v.w};
#pragma unroll
            for (int e = 0; e < 4; e++) {
                int c = lcb + u * 4 + e;
                int slab = c >> 3, cc = c & 7;
                int ln = ((r & 7) << 2) | (cc & 3);
                int slot = ((r >> 3) & 1) | ((cc >> 2) << 1);
                qf[wdst * 1024 + slab * 128 + ln * 4 + slot] = f2tf32(vv[e] * 0.03125f);
            }
        }
    }

    float o[8][4];
#pragma unroll
    for (int nf = 0; nf < 8; nf++)
#pragma unroll
        for (int e = 0; e < 4; e++) o[nf][e] = 0.f;
    float m0 = -1e30f, m1 = -1e30f, l0 = 0.f, l1 = 0.f;

    const size_t mbase = (size_t)b * SS * SS;
    unsigned* pw = pf + wq * 1024;

#pragma unroll 1
    for (int ch = 0; ch < 16; ++ch) {
        __syncthreads();
        {
            const float* kp = g_qkv + (size_t)(b * SS + ch * 64 + lrow) * QKVN + 1024 + h * DHH + lcb;
            const float* vp = kp + 1024;
            int nfK = lrow >> 3, nnK = lrow & 7;
            int slV = lrow >> 3, kkV = lrow & 7;
#pragma unroll
            for (int u = 0; u < 4; u++) {
                float4 v = ((const float4*)kp)[u];
                float vv[4] = {v.x, v.y, v.z, v.w};
#pragma unroll
                for (int e = 0; e < 4; e++) {
                    int c = lcb + u * 4 + e;
                    int slab = c >> 3, kk = c & 7;
                    kf[slab * 512 + nfK * 64 + (((nnK) << 2) | (kk & 3)) * 2 + (kk >> 2)] = f2tf32(vv[e]);
                }
            }
#pragma unroll
            for (int u = 0; u < 4; u++) {
                float4 v = ((const float4*)vp)[u];
                float vv[4] = {v.x, v.y, v.z, v.w};
#pragma unroll
                for (int e = 0; e < 4; e++) {
                    int c = lcb + u * 4 + e;
                    int nf = c >> 3, nn = c & 7;
                    vf[slV * 512 + nf * 64 + ((nn << 2) | (kkV & 3)) * 2 + (kkV >> 2)] = f2tf32(vv[e]);
                }
            }
        }
        __syncthreads();

        float s[8][4];
#pragma unroll
        for (int nf = 0; nf < 8; nf++)
#pragma unroll
            for (int e = 0; e < 4; e++) s[nf][e] = 0.f;
#pragma unroll
        for (int slab = 0; slab < 8; ++slab) {
            uint4 a = *(const uint4*)&qf[wq * 1024 + slab * 128 + lane * 4];
#pragma unroll
            for (int nf = 0; nf < 8; nf++) {
                uint2 bb = *(const uint2*)&kf[slab * 512 + nf * 64 + lane * 2];
                MMA_TF32(s[nf], a, bb);
            }
        }

        const int rg = q0 + wq * 16 + g;
        const int kb = ch * 64;
#pragma unroll
        for (int nf = 0; nf < 8; nf++) {
            int col = kb + nf * 8 + 2 * t;
            int2 mk0 = *(const int2*)(mask + mbase + (size_t)rg * SS + col);
            int2 mk1 = *(const int2*)(mask + mbase + (size_t)(rg + 8) * SS + col);
            if (mk0.x) s[nf][0] = -1e9f;
            if (mk0.y) s[nf][1] = -1e9f;
            if (mk1.x) s[nf][2] = -1e9f;
            if (mk1.y) s[nf][3] = -1e9f;
        }

        float mx0 = -1e30f, mx1 = -1e30f;
#pragma unroll
        for (int nf = 0; nf < 8; nf++) {
            mx0 = fmaxf(mx0, fmaxf(s[nf][0], s[nf][1]));
            mx1 = fmaxf(mx1, fmaxf(s[nf][2], s[nf][3]));
        }
        mx0 = fmaxf(mx0, __shfl_xor_sync(0xffffffffu, mx0, 1));
        mx0 = fmaxf(mx0, __shfl_xor_sync(0xffffffffu, mx0, 2));
        mx1 = fmaxf(mx1, __shfl_xor_sync(0xffffffffu, mx1, 1));
        mx1 = fmaxf(mx1, __shfl_xor_sync(0xffffffffu, mx1, 2));
        float mn0 = fmaxf(m0, mx0), mn1 = fmaxf(m1, mx1);
        float a0 = __expf(m0 - mn0), a1 = __expf(m1 - mn1);
        m0 = mn0; m1 = mn1;

        float p[8][4];
        float ps0 = 0.f, ps1 = 0.f;
#pragma unroll
        for (int nf = 0; nf < 8; nf++) {
            p[nf][0] = __expf(s[nf][0] - mn0);
            p[nf][1] = __expf(s[nf][1] - mn0);
            p[nf][2] = __expf(s[nf][2] - mn1);
            p[nf][3] = __expf(s[nf][3] - mn1);
            ps0 += p[nf][0] + p[nf][1];
            ps1 += p[nf][2] + p[nf][3];
        }
        ps0 += __shfl_xor_sync(0xffffffffu, ps0, 1);
        ps0 += __shfl_xor_sync(0xffffffffu, ps0, 2);
        ps1 += __shfl_xor_sync(0xffffffffu, ps1, 1);
        ps1 += __shfl_xor_sync(0xffffffffu, ps1, 2);
        l0 = l0 * a0 + ps0;
        l1 = l1 * a1 + ps1;
#pragma unroll
        for (int nf = 0; nf < 8; nf++) {
            o[nf][0] *= a0; o[nf][1] *= a0;
            o[nf][2] *= a1; o[nf][3] *= a1;
        }

        {
            int ln0 = (g << 2) | ((2 * t) & 3);
            int ln1 = (g << 2) | ((2 * t + 1) & 3);
            int sl  = (t >> 1) << 1;
#pragma unroll
            for (int nf = 0; nf < 8; nf++) {
                uint2 w0 = make_uint2(f2tf32(p[nf][0]), f2tf32(p[nf][2]));
                uint2 w1 = make_uint2(f2tf32(p[nf][1]), f2tf32(p[nf][3]));
                *(uint2*)&pw[nf * 128 + ln0 * 4 + sl] = w0;
                *(uint2*)&pw[nf * 128 + ln1 * 4 + sl] = w1;
            }
        }
        __syncwarp();

#pragma unroll
        for (int slab = 0; slab < 8; ++slab) {
            uint4 a = *(const uint4*)&pw[slab * 128 + lane * 4];
#pragma unroll
            for (int nf = 0; nf < 8; nf++) {
                uint2 bb = *(const uint2*)&vf[slab * 512 + nf * 64 + lane * 2];
                MMA_TF32(o[nf], a, bb);
            }
        }
    }

    float i0 = 1.f / l0, i1 = 1.f / l1;
    int row0 = q0 + wq * 16 + g;
#pragma unroll
    for (int nf = 0; nf < 8; nf++) {
        int col = h * DHH + nf * 8 + 2 * t;
        // tf32-round outputs: the projection GEMM consumes them as tf32 anyway
        float2 v0 = make_float2(__uint_as_float(f2tf32(o[nf][0] * i0)),
                                __uint_as_float(f2tf32(o[nf][1] * i0)));
        float2 v1 = make_float2(__uint_as_float(f2tf32(o[nf][2] * i1)),
                                __uint_as_float(f2tf32(o[nf][3] * i1)));
        *(float2*)(g_ctx + (size_t)(b * SS + row0) * DD + col)     = v0;
        *(float2*)(g_ctx + (size_t)(b * SS + row0 + 8) * DD + col) = v1;
    }
}

// ---------------- launch -----------------------------------------------------
extern "C" void kernel_launch(void* const* d_in, const int* in_sizes, int n_in,
                              void* d_out, int out_size)
{
    const float* x  = (const float*)d_in[0];
    const int* mask = (const int*)d_in[1];
    const float* Wq = (const float*)d_in[2];
    const float* bq = (const float*)d_in[3];
    const float* Wk = (const float*)d_in[4];
    const float* bk = (const float*)d_in[5];
    const float* Wv = (const float*)d_in[6];
    const float* bv = (const float*)d_in[7];
    const float* Wo = (const float*)d_in[8];
    const float* bo = (const float*)d_in[9];
    float* out = (float*)d_out;

    void *p_w, *p_b, *p_qkv, *p_ctx, *p_xt, *p_wo;
    cudaGetSymbolAddress(&p_w, g_w);
    cudaGetSymbolAddress(&p_b, g_b);
    cudaGetSymbolAddress(&p_qkv, g_qkv);
    cudaGetSymbolAddress(&p_ctx, g_ctx);
    cudaGetSymbolAddress(&p_xt, g_xt);
    cudaGetSymbolAddress(&p_wo, g_wo);

    const int ATTN_SMEM = 24576 * (int)sizeof(unsigned);   // 96KB
    const int GEMM_SMEM = 4 * 6144 * (int)sizeof(unsigned); // 96KB
    static int smem_set = 0;
    if (!smem_set) {
        cudaFuncSetAttribute(attn_mma_kernel, cudaFuncAttributeMaxDynamicSharedMemorySize, ATTN_SMEM);
        cudaFuncSetAttribute(tf32_gemm_bias, cudaFuncAttributeMaxDynamicSharedMemorySize, GEMM_SMEM);
        smem_set = 1;
    }

    // tf32-round inputs & Wo; pack+round QKV weights
    round_tf32_kernel<<<(MROWS * KDIM / 4 + 255) / 256, 256>>>(
        (const float4*)x, (float4*)p_xt, MROWS * KDIM / 4);
    round_tf32_kernel<<<(KDIM * DD / 4 + 255) / 256, 256>>>(
        (const float4*)Wo, (float4*)p_wo, KDIM * DD / 4);
    pack_w_kernel<<<(KDIM * QKVN + 255) / 256, 256>>>(Wq, bq, Wk, bk, Wv, bv);

    // QKV projection
    tf32_gemm_bias<<<dim3(QKVN / 256, MROWS / 128), 256, GEMM_SMEM>>>(
        (const float*)p_xt, (const float*)p_w, (const float*)p_b, (float*)p_qkv,
        MROWS, QKVN, KDIM);

    // fused masked attention
    attn_mma_kernel<<<dim3(SS / 128, BB * HH), 256, ATTN_SMEM>>>(mask);

    // output projection
    tf32_gemm_bias<<<dim3(DD / 256, MROWS / 128), 256, GEMM_SMEM>>>(
        (const float*)p_ctx, (const float*)p_wo, bo, out, MROWS, DD, KDIM);
}

// round 9
// speedup vs baseline: 5.2840x; 1.0855x over previous
#include <cuda_runtime.h>
#include <cstdint>

#define BB 8
#define SS 1024
#define DD 1024
#define HH 16
#define DHH 64
#define QKVN 3072
#define MROWS 8192
#define KDIM 1024

// ---------------- scratch ----------------------------------------------------
__device__ float g_w[KDIM * QKVN];                 // packed QKV weights (tf32-rounded)
__device__ float g_b[QKVN];
__device__ float g_qkv[(size_t)MROWS * QKVN];      // tf32-rounded (GEMM epilogue)
__device__ float g_ctx[(size_t)MROWS * DD];        // tf32-rounded (attn epilogue)
__device__ float g_xt[(size_t)MROWS * KDIM];       // tf32-rounded inputs
__device__ float g_wo[KDIM * DD];                  // tf32-rounded Wo

// ---------------- tf32 helpers ----------------------------------------------
__device__ __forceinline__ unsigned f2tf32(float x) {
    unsigned u;
    asm("cvt.rna.tf32.f32 %0, %1;" : "=r"(u) : "f"(x));
    return u;
}

#define MMA_TF32(c, a, b)                                                     \
    asm volatile("mma.sync.aligned.m16n8k8.row.col.f32.tf32.tf32.f32 "        \
                 "{%0,%1,%2,%3}, {%4,%5,%6,%7}, {%8,%9}, {%0,%1,%2,%3};"      \
                 : "+f"((c)[0]), "+f"((c)[1]), "+f"((c)[2]), "+f"((c)[3])     \
                 : "r"((a).x), "r"((a).y), "r"((a).z), "r"((a).w),            \
                   "r"((b).x), "r"((b).y))

#define CPA16(dst, src)                                                       \
    asm volatile("cp.async.cg.shared.global [%0], [%1], 16;"                  \
                 :: "r"(dst), "l"(__cvta_generic_to_global(src)))
#define CP_COMMIT() asm volatile("cp.async.commit_group;")

// ---------------- pack Wq/Wk/Wv [H,D,DH] -> g_w [D][3*H*DH] (tf32) -----------
__global__ void pack_w_kernel(const float* __restrict__ Wq, const float* __restrict__ bq,
                              const float* __restrict__ Wk, const float* __restrict__ bk,
                              const float* __restrict__ Wv, const float* __restrict__ bv)
{
    int idx = blockIdx.x * 256 + threadIdx.x;
    if (idx < KDIM * QKVN) {
        int d   = idx / QKVN;
        int col = idx - d * QKVN;
        int which = col >> 10;
        int he  = col & 1023;
        int h   = he >> 6;
        int e   = he & 63;
        const float* W = (which == 0) ? Wq : ((which == 1) ? Wk : Wv);
        g_w[idx] = __uint_as_float(f2tf32(W[(h * KDIM + d) * DHH + e]));
    }
    if (idx < QKVN) {
        int which = idx >> 10;
        int he = idx & 1023;
        const float* bb = (which == 0) ? bq : ((which == 1) ? bk : bv);
        g_b[idx] = bb[he];
    }
}

// ---------------- elementwise tf32 rounding ----------------------------------
__global__ void round_tf32_kernel(const float4* __restrict__ in, float4* __restrict__ out, int n4)
{
    int i = blockIdx.x * 256 + threadIdx.x;
    if (i < n4) {
        float4 v = in[i];
        v.x = __uint_as_float(f2tf32(v.x));
        v.y = __uint_as_float(f2tf32(v.y));
        v.z = __uint_as_float(f2tf32(v.z));
        v.w = __uint_as_float(f2tf32(v.w));
        out[i] = v;
    }
}

// ---------------- tf32 GEMM v4: cp.async 4-stage, 128x256, 64x64 warps -------
// roundC: tf32-round outputs (for g_qkv, consumed raw by attention MMAs)
__global__ __launch_bounds__(256, 1)
void tf32_gemm_bias(const float* __restrict__ A, const float* __restrict__ Bm,
                    const float* __restrict__ bias, float* __restrict__ C,
                    int M, int N, int K, int roundC)
{
    extern __shared__ unsigned S[];   // 4 * 6144 words = 96KB

    const int tid  = threadIdx.x;
    const int lane = tid & 31;
    const int wid  = tid >> 5;
    const int wm   = wid >> 2;
    const int wn   = wid & 3;
    const int bm   = blockIdx.y * 128;
    const int bn   = blockIdx.x * 256;
    const int g    = lane >> 2;
    const int t    = lane & 3;

    unsigned sbase;
    asm("{ .reg .u64 x0; cvta.to.shared.u64 x0, %1; cvt.u32.u64 %0, x0; }"
        : "=r"(sbase) : "l"(S));

    const int arow = tid >> 2;
    const int ac   = tid & 3;
    const int swA  = (arow >> 1) & 3;
    const float* Asrc = A + (size_t)(bm + arow) * K + 4 * ac;
    const unsigned adst0 = sbase + (unsigned)(arow * 16 + ((ac ^ swA) & 3) * 4) * 4;
    const unsigned adst1 = adst0 + 64 * 16 * 4;

    const int kb = tid >> 4;
    const int bc = tid & 15;
    const int sB = (2 * kb) & 7;
    const float* Bsrc = Bm + (size_t)kb * N + bn + 4 * bc;
    unsigned bdst[4];
#pragma unroll
    for (int u = 0; u < 4; u++)
        bdst[u] = sbase + (unsigned)(2048 + kb * 256 + (((bc + 16 * u) ^ sB) & 63) * 4) * 4;

#define GEMM_ISSUE(it, stg) do {                                               \
        unsigned off_ = (unsigned)(stg) * 24576u;                              \
        const float* as_ = Asrc + (size_t)(it) * 16;                           \
        CPA16(adst0 + off_, as_);                                              \
        CPA16(adst1 + off_, as_ + (size_t)64 * K);                             \
        const float* bs_ = Bsrc + (size_t)(it) * 16 * N;                       \
        CPA16(bdst[0] + off_, bs_);                                            \
        CPA16(bdst[1] + off_, bs_ + 64);                                       \
        CPA16(bdst[2] + off_, bs_ + 128);                                      \
        CPA16(bdst[3] + off_, bs_ + 192);                                      \
    } while (0)

    float acc[4][8][4];
#pragma unroll
    for (int m = 0; m < 4; m++)
#pragma unroll
        for (int nf = 0; nf < 8; nf++)
#pragma unroll
            for (int e = 0; e < 4; e++) acc[m][nf][e] = 0.f;

    GEMM_ISSUE(0, 0); CP_COMMIT();
    GEMM_ISSUE(1, 1); CP_COMMIT();
    GEMM_ISSUE(2, 2); CP_COMMIT();

    const int NIT = K >> 4;
    const int swa = (g >> 1) & 3;

    for (int it = 0; it < NIT; ++it) {
        asm volatile("cp.async.wait_group 2;");
        __syncthreads();
        if (it + 3 < NIT) GEMM_ISSUE(it + 3, (it + 3) & 3);
        CP_COMMIT();

        const unsigned* Sa = S + (it & 3) * 6144;
        const unsigned* Sb = Sa + 2048;

#pragma unroll
        for (int sl = 0; sl < 2; ++sl) {
            uint4 af[4];
            const int cx = ((2 * sl) ^ swa) << 2;
            const int cz = ((2 * sl + 1) ^ swa) << 2;
#pragma unroll
            for (int m = 0; m < 4; m++) {
                int rb = (wm * 64 + m * 16 + g) * 16 + t;
                af[m].x = Sa[rb + cx];
                af[m].y = Sa[rb + 128 + cx];
                af[m].z = Sa[rb + cz];
                af[m].w = Sa[rb + 128 + cz];
            }
            uint2 bf[8];
            const int r0 = (sl * 8 + t) * 256 + (g & 3);
            const int r1 = r0 + 4 * 256;
#pragma unroll
            for (int nf = 0; nf < 8; nf++) {
                int c2 = ((wn * 16 + nf * 2 + (g >> 2)) ^ (2 * t)) & 63;
                bf[nf].x = Sb[r0 + c2 * 4];
                bf[nf].y = Sb[r1 + c2 * 4];
            }
#pragma unroll
            for (int m = 0; m < 4; m++)
#pragma unroll
                for (int nf = 0; nf < 8; nf++)
                    MMA_TF32(acc[m][nf], af[m], bf[nf]);
        }
    }

    // ---- epilogue
#pragma unroll
    for (int m = 0; m < 4; m++) {
        int row = bm + wm * 64 + m * 16 + g;
#pragma unroll
        for (int nf = 0; nf < 8; nf++) {
            int col = bn + wn * 64 + nf * 8 + 2 * t;
            float b0 = bias[col], b1 = bias[col + 1];
            float2 v0 = make_float2(acc[m][nf][0] + b0, acc[m][nf][1] + b1);
            float2 v1 = make_float2(acc[m][nf][2] + b0, acc[m][nf][3] + b1);
            if (roundC) {
                v0.x = __uint_as_float(f2tf32(v0.x));
                v0.y = __uint_as_float(f2tf32(v0.y));
                v1.x = __uint_as_float(f2tf32(v1.x));
                v1.y = __uint_as_float(f2tf32(v1.y));
            }
            *(float2*)&C[(size_t)row * N + col]       = v0;
            *(float2*)&C[(size_t)(row + 8) * N + col] = v1;
        }
    }
#undef GEMM_ISSUE
}

// ---------------- attention v3: cp.async K/V, Q frags in registers -----------
// grid (S/128, B*H), 256 threads. Smem words:
//   pf [0,8192)   P frags, per warp 1024
//   kb [8192, 8192+2*4352)   K chunks, natural [64][68], double-buffered
//   vb [16896, 16896+2*4352) V chunks
__global__ __launch_bounds__(256)
void attn_mma_kernel(const int* __restrict__ mask)
{
    extern __shared__ unsigned sm_u[];
    unsigned* pf = sm_u;

    const int tid  = threadIdx.x;
    const int lane = tid & 31;
    const int wq   = tid >> 5;
    const int g    = lane >> 2;
    const int t    = lane & 3;
    const int b    = blockIdx.y >> 4;
    const int h    = blockIdx.y & 15;
    const int q0   = blockIdx.x * 128;

    unsigned sbase;
    asm("{ .reg .u64 x0; cvta.to.shared.u64 x0, %1; cvt.u32.u64 %0, x0; }"
        : "=r"(sbase) : "l"(sm_u));

    // ---- Q fragments in registers (g_qkv is tf32-rounded; *2^-5 preserves it)
    uint4 qreg[8];
    {
        const float* qb = g_qkv + ((size_t)(b * SS + q0 + wq * 16)) * QKVN + h * DHH;
#pragma unroll
        for (int sl = 0; sl < 8; sl++) {
            float x0 = qb[(size_t)g * QKVN + sl * 8 + t];
            float x1 = qb[(size_t)(g + 8) * QKVN + sl * 8 + t];
            float x2 = qb[(size_t)g * QKVN + sl * 8 + t + 4];
            float x3 = qb[(size_t)(g + 8) * QKVN + sl * 8 + t + 4];
            qreg[sl].x = __float_as_uint(x0 * 0.03125f);
            qreg[sl].y = __float_as_uint(x1 * 0.03125f);
            qreg[sl].z = __float_as_uint(x2 * 0.03125f);
            qreg[sl].w = __float_as_uint(x3 * 0.03125f);
        }
    }

    // ---- cp.async mappings: thread -> K/V row krow, 16B quarter kq
    const int krow = tid >> 2;
    const int kq   = tid & 3;
    const size_t srcrow = ((size_t)(b * SS) + krow) * QKVN + h * DHH + kq * 4;
    const unsigned kdst = sbase + (unsigned)(8192 + krow * 68 + kq * 4) * 4;
    const unsigned vdst = sbase + (unsigned)(16896 + krow * 68 + kq * 4) * 4;

#define AT_ISSUE(ch) do {                                                      \
        unsigned bo_ = ((ch) & 1) ? 17408u : 0u;                               \
        const float* kp_ = g_qkv + srcrow + (size_t)(ch) * 64 * QKVN + 1024;   \
        const float* vp_ = kp_ + 1024;                                         \
        CPA16(kdst + bo_,       kp_);                                          \
        CPA16(kdst + bo_ + 64,  kp_ + 16);                                     \
        CPA16(kdst + bo_ + 128, kp_ + 32);                                     \
        CPA16(kdst + bo_ + 192, kp_ + 48);                                     \
        CPA16(vdst + bo_,       vp_);                                          \
        CPA16(vdst + bo_ + 64,  vp_ + 16);                                     \
        CPA16(vdst + bo_ + 128, vp_ + 32);                                     \
        CPA16(vdst + bo_ + 192, vp_ + 48);                                     \
        CP_COMMIT();                                                           \
    } while (0)

    float o[8][4];
#pragma unroll
    for (int nf = 0; nf < 8; nf++)
#pragma unroll
        for (int e = 0; e < 4; e++) o[nf][e] = 0.f;
    float m0 = -1e30f, m1 = -1e30f, l0 = 0.f, l1 = 0.f;

    const size_t mbase = (size_t)b * SS * SS;
    unsigned* pw = pf + wq * 1024;

    AT_ISSUE(0);

#pragma unroll 1
    for (int ch = 0; ch < 16; ++ch) {
        if (ch + 1 < 16) {
            AT_ISSUE(ch + 1);
            asm volatile("cp.async.wait_group 1;");
        } else {
            asm volatile("cp.async.wait_group 0;");
        }
        __syncthreads();

        const unsigned* KS = sm_u + 8192  + ((ch & 1) ? 4352 : 0);
        const unsigned* VS = sm_u + 16896 + ((ch & 1) ? 4352 : 0);

        // ---- GEMM1: S[16 q][64 keys], B-frags straight from natural K
        float s[8][4];
#pragma unroll
        for (int nf = 0; nf < 8; nf++)
#pragma unroll
            for (int e = 0; e < 4; e++) s[nf][e] = 0.f;
#pragma unroll
        for (int sl = 0; sl < 8; ++sl) {
            const int ab = g * 68 + sl * 8 + t;
#pragma unroll
            for (int nf = 0; nf < 8; nf++) {
                uint2 bb;
                bb.x = KS[nf * 544 + ab];
                bb.y = KS[nf * 544 + ab + 4];
                MMA_TF32(s[nf], qreg[sl], bb);
            }
        }

        // ---- mask (nonzero -> -1e9)
        const int rg = q0 + wq * 16 + g;
        const int kb = ch * 64;
#pragma unroll
        for (int nf = 0; nf < 8; nf++) {
            int col = kb + nf * 8 + 2 * t;
            int2 mk0 = *(const int2*)(mask + mbase + (size_t)rg * SS + col);
            int2 mk1 = *(const int2*)(mask + mbase + (size_t)(rg + 8) * SS + col);
            if (mk0.x) s[nf][0] = -1e9f;
            if (mk0.y) s[nf][1] = -1e9f;
            if (mk1.x) s[nf][2] = -1e9f;
            if (mk1.y) s[nf][3] = -1e9f;
        }

        // ---- online softmax (row stats across 4-lane quad)
        float mx0 = -1e30f, mx1 = -1e30f;
#pragma unroll
        for (int nf = 0; nf < 8; nf++) {
            mx0 = fmaxf(mx0, fmaxf(s[nf][0], s[nf][1]));
            mx1 = fmaxf(mx1, fmaxf(s[nf][2], s[nf][3]));
        }
        mx0 = fmaxf(mx0, __shfl_xor_sync(0xffffffffu, mx0, 1));
        mx0 = fmaxf(mx0, __shfl_xor_sync(0xffffffffu, mx0, 2));
        mx1 = fmaxf(mx1, __shfl_xor_sync(0xffffffffu, mx1, 1));
        mx1 = fmaxf(mx1, __shfl_xor_sync(0xffffffffu, mx1, 2));
        float mn0 = fmaxf(m0, mx0), mn1 = fmaxf(m1, mx1);
        float a0 = __expf(m0 - mn0), a1 = __expf(m1 - mn1);
        m0 = mn0; m1 = mn1;

        float p[8][4];
        float ps0 = 0.f, ps1 = 0.f;
#pragma unroll
        for (int nf = 0; nf < 8; nf++) {
            p[nf][0] = __expf(s[nf][0] - mn0);
            p[nf][1] = __expf(s[nf][1] - mn0);
            p[nf][2] = __expf(s[nf][2] - mn1);
            p[nf][3] = __expf(s[nf][3] - mn1);
            ps0 += p[nf][0] + p[nf][1];
            ps1 += p[nf][2] + p[nf][3];
        }
        ps0 += __shfl_xor_sync(0xffffffffu, ps0, 1);
        ps0 += __shfl_xor_sync(0xffffffffu, ps0, 2);
        ps1 += __shfl_xor_sync(0xffffffffu, ps1, 1);
        ps1 += __shfl_xor_sync(0xffffffffu, ps1, 2);
        l0 = l0 * a0 + ps0;
        l1 = l1 * a1 + ps1;
#pragma unroll
        for (int nf = 0; nf < 8; nf++) {
            o[nf][0] *= a0; o[nf][1] *= a0;
            o[nf][2] *= a1; o[nf][3] *= a1;
        }

        // ---- P -> per-warp A-frag smem (STS.64 pairs), syncwarp only
        {
            int ln0 = (g << 2) | ((2 * t) & 3);
            int ln1 = (g << 2) | ((2 * t + 1) & 3);
            int sl  = (t >> 1) << 1;
#pragma unroll
            for (int nf = 0; nf < 8; nf++) {
                uint2 w0 = make_uint2(f2tf32(p[nf][0]), f2tf32(p[nf][2]));
                uint2 w1 = make_uint2(f2tf32(p[nf][1]), f2tf32(p[nf][3]));
                *(uint2*)&pw[nf * 128 + ln0 * 4 + sl] = w0;
                *(uint2*)&pw[nf * 128 + ln1 * 4 + sl] = w1;
            }
        }
        __syncwarp();

        // ---- GEMM2: O += P @ V, B-frags straight from natural V
#pragma unroll
        for (int sl = 0; sl < 8; ++sl) {
            uint4 a = *(const uint4*)&pw[sl * 128 + lane * 4];
            const int vb = (sl * 8 + t) * 68 + g;
#pragma unroll
            for (int nf = 0; nf < 8; nf++) {
                uint2 bb;
                bb.x = VS[vb + nf * 8];
                bb.y = VS[vb + nf * 8 + 4 * 68];
                MMA_TF32(o[nf], a, bb);
            }
        }
        __syncthreads();   // buffers safe to overwrite next iteration
    }

    // ---- epilogue (tf32-rounded for the out-proj GEMM)
    float i0 = 1.f / l0, i1 = 1.f / l1;
    int row0 = q0 + wq * 16 + g;
#pragma unroll
    for (int nf = 0; nf < 8; nf++) {
        int col = h * DHH + nf * 8 + 2 * t;
        float2 v0 = make_float2(__uint_as_float(f2tf32(o[nf][0] * i0)),
                                __uint_as_float(f2tf32(o[nf][1] * i0)));
        float2 v1 = make_float2(__uint_as_float(f2tf32(o[nf][2] * i1)),
                                __uint_as_float(f2tf32(o[nf][3] * i1)));
        *(float2*)(g_ctx + (size_t)(b * SS + row0) * DD + col)     = v0;
        *(float2*)(g_ctx + (size_t)(b * SS + row0 + 8) * DD + col) = v1;
    }
#undef AT_ISSUE
}

// ---------------- launch -----------------------------------------------------
extern "C" void kernel_launch(void* const* d_in, const int* in_sizes, int n_in,
                              void* d_out, int out_size)
{
    const float* x  = (const float*)d_in[0];
    const int* mask = (const int*)d_in[1];
    const float* Wq = (const float*)d_in[2];
    const float* bq = (const float*)d_in[3];
    const float* Wk = (const float*)d_in[4];
    const float* bk = (const float*)d_in[5];
    const float* Wv = (const float*)d_in[6];
    const float* bv = (const float*)d_in[7];
    const float* Wo = (const float*)d_in[8];
    const float* bo = (const float*)d_in[9];
    float* out = (float*)d_out;

    void *p_w, *p_b, *p_qkv, *p_ctx, *p_xt, *p_wo;
    cudaGetSymbolAddress(&p_w, g_w);
    cudaGetSymbolAddress(&p_b, g_b);
    cudaGetSymbolAddress(&p_qkv, g_qkv);
    cudaGetSymbolAddress(&p_ctx, g_ctx);
    cudaGetSymbolAddress(&p_xt, g_xt);
    cudaGetSymbolAddress(&p_wo, g_wo);

    const int ATTN_SMEM = 25600 * (int)sizeof(unsigned);     // 100KB
    const int GEMM_SMEM = 4 * 6144 * (int)sizeof(unsigned);  // 96KB
    static int smem_set = 0;
    if (!smem_set) {
        cudaFuncSetAttribute(attn_mma_kernel, cudaFuncAttributeMaxDynamicSharedMemorySize, ATTN_SMEM);
        cudaFuncSetAttribute(tf32_gemm_bias, cudaFuncAttributeMaxDynamicSharedMemorySize, GEMM_SMEM);
        smem_set = 1;
    }

    round_tf32_kernel<<<(MROWS * KDIM / 4 + 255) / 256, 256>>>(
        (const float4*)x, (float4*)p_xt, MROWS * KDIM / 4);
    round_tf32_kernel<<<(KDIM * DD / 4 + 255) / 256, 256>>>(
        (const float4*)Wo, (float4*)p_wo, KDIM * DD / 4);
    pack_w_kernel<<<(KDIM * QKVN + 255) / 256, 256>>>(Wq, bq, Wk, bk, Wv, bv);

    // QKV projection -> tf32-rounded (attention consumes raw as MMA operands)
    tf32_gemm_bias<<<dim3(QKVN / 256, MROWS / 128), 256, GEMM_SMEM>>>(
        (const float*)p_xt, (const float*)p_w, (const float*)p_b, (float*)p_qkv,
        MROWS, QKVN, KDIM, 1);

    // fused masked attention
    attn_mma_kernel<<<dim3(SS / 128, BB * HH), 256, ATTN_SMEM>>>(mask);

    // output projection -> full fp32 output
    tf32_gemm_bias<<<dim3(DD / 256, MROWS / 128), 256, GEMM_SMEM>>>(
        (const float*)p_ctx, (const float*)p_wo, bo, out, MROWS, DD, KDIM, 0);
}